// round 12
// baseline (speedup 1.0000x reference)
#include <cuda_runtime.h>
#include <cuda_bf16.h>
#include <math.h>
#include <stdint.h>

// Problem constants
#define Bx 2
#define Sx 2048
#define Dx 2048
#define Hx 16
#define HDx 128
#define Mx (Bx*Sx)   // 4096

// Scratch (device globals; no allocation allowed)
__device__ float g_q[(size_t)Mx * Dx];
__device__ float g_k[(size_t)Mx * Dx];
__device__ float g_v[(size_t)Mx * Dx];
// bf16 split buffers: hb/hs receive split(ctx) from flash (Wo GEMM input).
__device__ uint32_t g_hb[(size_t)Mx * Dx / 2];
__device__ uint32_t g_hs[(size_t)Mx * Dx / 2];
// Wo weight bf16 split (K-major)
__device__ uint32_t g_wob[(size_t)Dx * Dx / 2];
__device__ uint32_t g_wos[(size_t)Dx * Dx / 2];
// int8 2-term quant buffers (packed 4 s8 per word along K).
__device__ uint32_t g_a8h[(size_t)Mx * Dx / 4];
__device__ uint32_t g_a8l[(size_t)Mx * Dx / 4];
__device__ uint32_t g_wq8h[(size_t)Dx * Dx / 4];
__device__ uint32_t g_wq8l[(size_t)Dx * Dx / 4];
__device__ uint32_t g_wk8h[(size_t)Dx * Dx / 4];
__device__ uint32_t g_wk8l[(size_t)Dx * Dx / 4];
__device__ uint32_t g_wv8h[(size_t)Dx * Dx / 4];
__device__ uint32_t g_wv8l[(size_t)Dx * Dx / 4];
// per-row / per-col quant scales
__device__ float g_sA[Mx];
__device__ float g_sq[Dx];
__device__ float g_sk[Dx];
__device__ float g_sv[Dx];
// Flash operands
__device__ uint32_t g_qsb[(size_t)32 * 2048 * 64];
__device__ uint32_t g_qss[(size_t)32 * 2048 * 64];
__device__ uint32_t g_ksb[(size_t)32 * 2048 * 64];
__device__ uint32_t g_kss[(size_t)32 * 2048 * 64];
__device__ uint32_t g_vtb[(size_t)32 * 128 * 1024];
__device__ uint32_t g_vts[(size_t)32 * 128 * 1024];

// ---------------------------------------------------------------------------
// Helpers
// ---------------------------------------------------------------------------
__device__ __forceinline__ void cpa16(void* smem, const void* gmem) {
    uint32_t s = (uint32_t)__cvta_generic_to_shared(smem);
    asm volatile("cp.async.cg.shared.global [%0], [%1], 16;\n" :: "r"(s), "l"(gmem));
}
__device__ __forceinline__ void cpa_commit() {
    asm volatile("cp.async.commit_group;\n");
}
__device__ __forceinline__ uint16_t f2bf(float x) {
    __nv_bfloat16 h = __float2bfloat16_rn(x);
    return *(uint16_t*)&h;
}
__device__ __forceinline__ float bf2f(uint16_t b) {
    __nv_bfloat16 h = *(__nv_bfloat16*)&b;
    return __bfloat162float(h);
}
__device__ __forceinline__ void split_bf(float x, uint16_t& big, uint16_t& sml) {
    big = f2bf(x);
    sml = f2bf(x - bf2f(big));
}
__device__ __forceinline__ void pack_split(float x, float y, uint32_t& bb, uint32_t& ss) {
    uint16_t bx, sx, by, sy;
    split_bf(x, bx, sx); split_bf(y, by, sy);
    bb = (uint32_t)bx | ((uint32_t)by << 16);
    ss = (uint32_t)sx | ((uint32_t)sy << 16);
}
__device__ __forceinline__ void mma_bf16(float c[4], const uint32_t a[4], const uint32_t b[2]) {
    asm volatile(
        "mma.sync.aligned.m16n8k16.row.col.f32.bf16.bf16.f32 "
        "{%0,%1,%2,%3},{%4,%5,%6,%7},{%8,%9},{%0,%1,%2,%3};\n"
        : "+f"(c[0]), "+f"(c[1]), "+f"(c[2]), "+f"(c[3])
        : "r"(a[0]), "r"(a[1]), "r"(a[2]), "r"(a[3]), "r"(b[0]), "r"(b[1]));
}
__device__ __forceinline__ void mma_s8(int c[4], const uint32_t a[4], const uint32_t b[2]) {
    asm volatile(
        "mma.sync.aligned.m16n8k32.row.col.s32.s8.s8.s32 "
        "{%0,%1,%2,%3},{%4,%5,%6,%7},{%8,%9},{%0,%1,%2,%3};\n"
        : "+r"(c[0]), "+r"(c[1]), "+r"(c[2]), "+r"(c[3])
        : "r"(a[0]), "r"(a[1]), "r"(a[2]), "r"(a[3]), "r"(b[0]), "r"(b[1]));
}
// quantize 4 floats to packed h-word and l-word: x ~= s*(128*h + l)
__device__ __forceinline__ void quant4(const float* x, float inv, uint32_t& hw, uint32_t& lw) {
    hw = 0; lw = 0;
#pragma unroll
    for (int i = 0; i < 4; ++i) {
        float Q = x[i] * inv;
        int h = __float2int_rn(Q * 0.0078125f);   // /128
        int l = __float2int_rn(Q - 128.0f * (float)h);
        hw |= ((uint32_t)h & 0xFFu) << (8 * i);
        lw |= ((uint32_t)l & 0xFFu) << (8 * i);
    }
}

// ---------------------------------------------------------------------------
// quant_rows: X[M][2048] fp32 -> h/l packed words [M][512], sA[M].
// One block per row, 256 threads x 8 elems.
// ---------------------------------------------------------------------------
__global__ __launch_bounds__(256)
void quant_rows(const float* __restrict__ X, uint32_t* __restrict__ Hw,
                uint32_t* __restrict__ Lw, float* __restrict__ sA) {
    __shared__ float red[256];
    const int row = blockIdx.x;
    const int tid = threadIdx.x;
    const float* xr = X + (size_t)row * Dx;
    float x[8];
#pragma unroll
    for (int i = 0; i < 8; ++i) x[i] = xr[tid * 8 + i];
    float mx = 0.f;
#pragma unroll
    for (int i = 0; i < 8; ++i) mx = fmaxf(mx, fabsf(x[i]));
    red[tid] = mx;
    __syncthreads();
    for (int o = 128; o; o >>= 1) {
        if (tid < o) red[tid] = fmaxf(red[tid], red[tid + o]);
        __syncthreads();
    }
    float rmax = fmaxf(red[0], 1e-30f);
    float inv = 16256.0f / rmax;
    if (tid == 0) sA[row] = rmax / 16256.0f;
    uint32_t hw, lw;
    quant4(x,     inv, hw, lw);
    Hw[(size_t)row * 512 + tid * 2]     = hw;
    Lw[(size_t)row * 512 + tid * 2]     = lw;
    quant4(x + 4, inv, hw, lw);
    Hw[(size_t)row * 512 + tid * 2 + 1] = hw;
    Lw[(size_t)row * 512 + tid * 2 + 1] = lw;
}

// ---------------------------------------------------------------------------
// colmax_scale: W[K][N] -> sB[n] = colmax/16256. grid N/256, block 256.
// ---------------------------------------------------------------------------
__global__ __launch_bounds__(256)
void colmax_scale(const float* __restrict__ W, float* __restrict__ sB) {
    int col = blockIdx.x * 256 + threadIdx.x;
    float m = 0.f;
    for (int kk = 0; kk < Dx; ++kk)
        m = fmaxf(m, fabsf(W[(size_t)kk * Dx + col]));
    sB[col] = fmaxf(m, 1e-30f) / 16256.0f;
}

// ---------------------------------------------------------------------------
// quantT8: W[K][N] fp32 -> Hw/Lw [N][K/4 words] (transposed, packed s8x4).
// 32x32 tiles, 256 threads.
// ---------------------------------------------------------------------------
__global__ __launch_bounds__(256)
void quantT8(const float* __restrict__ W, const float* __restrict__ sB,
             uint32_t* __restrict__ Hw, uint32_t* __restrict__ Lw) {
    __shared__ float t[32][33];        // t[k_local][n_local]
    int n0 = blockIdx.x * 32, k0 = blockIdx.y * 32;
    int tx = threadIdx.x & 31, ty = threadIdx.x >> 5;
#pragma unroll
    for (int i = 0; i < 4; ++i)
        t[ty + i * 8][tx] = W[(size_t)(k0 + ty + i * 8) * Dx + n0 + tx];
    __syncthreads();
    int nl = threadIdx.x >> 3;         // 0..31
    int wq = threadIdx.x & 7;          // word 0..7 (4 k-elems each)
    float inv = 1.0f / sB[n0 + nl] * (1.0f / 16256.0f) * 16256.0f;  // == 1/sB
    inv = 1.0f / sB[n0 + nl];
    // note: quant4 expects inv mapping x -> Q with |Q|<=16256; x*inv where
    // inv = 1/sB = 16256/colmax. Correct.
    float xv[4];
#pragma unroll
    for (int i = 0; i < 4; ++i) xv[i] = t[4 * wq + i][nl];
    uint32_t hw, lw;
    quant4(xv, inv, hw, lw);
    size_t o = (size_t)(n0 + nl) * (Dx / 4) + (k0 / 4) + wq;
    Hw[o] = hw; Lw[o] = lw;
}

// ---------------------------------------------------------------------------
// INT8 2-term GEMM: C[M,N] = A @ W^T via 3 s8 mmas per k32 region.
// 128x128 tile, KT=64, 512 threads = 16 warps (4m x 4n), 32x32 per warp.
// A[M][K/4 words] h/l; B[N][K/4 words] h/l. D = sA*sB*(16384*acc1+128*acc2).
// Writes [B,H,S,HD] (BN=128 = 1 head = blockIdx.x).
// ---------------------------------------------------------------------------
#define I_LDW 20
#define IA_W (128 * I_LDW)            // 2560 words per term
#define ISTG_W (4 * IA_W)             // 10240 words per stage (Ah Al Bh Bl)
#define IGEMM_DYN (2 * ISTG_W * 4)    // 81920 bytes

__global__ __launch_bounds__(512)
void igemm128(const uint32_t* __restrict__ Ah, const uint32_t* __restrict__ Al,
              const uint32_t* __restrict__ Bh, const uint32_t* __restrict__ Bl,
              const float* __restrict__ sA, const float* __restrict__ sB,
              float* __restrict__ C) {
    extern __shared__ uint32_t sm[];
    const int tid  = threadIdx.x;
    const int lane = tid & 31;
    const int warp = tid >> 5;        // 0..15
    const int wm   = warp & 3;        // 4 m-quarters of 32
    const int wn   = warp >> 2;       // 4 n-quarters of 32

    const int KW = Dx / 4;            // 512 words per row
    const size_t aoff = (size_t)blockIdx.y * 128 * KW;
    const size_t boff = (size_t)blockIdx.x * 128 * KW;

    int acc1[2][4][4], acc2[2][4][4];
#pragma unroll
    for (int i = 0; i < 2; ++i)
#pragma unroll
        for (int j = 0; j < 4; ++j)
#pragma unroll
            for (int t = 0; t < 4; ++t) { acc1[i][j][t] = 0; acc2[i][j][t] = 0; }

    // Stage: Ah[IA_W] Al[IA_W] Bh[IA_W] Bl[IA_W]
    auto loadTiles = [&](int kt, int stg) {      // kt in elements (mult of 64)
        uint32_t* sb = sm + stg * ISTG_W;
        const int kw = kt / 4;                   // 16 words per row-chunk
        int r = tid >> 2, o = (tid & 3) << 2;
        int s = r * I_LDW + o;
        cpa16(sb + s,            Ah + aoff + (size_t)r * KW + kw + o);
        cpa16(sb + IA_W + s,     Al + aoff + (size_t)r * KW + kw + o);
        cpa16(sb + 2 * IA_W + s, Bh + boff + (size_t)r * KW + kw + o);
        cpa16(sb + 3 * IA_W + s, Bl + boff + (size_t)r * KW + kw + o);
    };

    const int NT = Dx / 64;           // 32 chunks
    loadTiles(0, 0); cpa_commit();

    for (int it = 0; it < NT; ++it) {
        if (it + 1 < NT) {
            loadTiles((it + 1) * 64, (it + 1) & 1);
            cpa_commit();
            asm volatile("cp.async.wait_group 1;\n" ::: "memory");
        } else {
            asm volatile("cp.async.wait_group 0;\n" ::: "memory");
        }
        __syncthreads();

        const uint32_t* Ahp = sm + (it & 1) * ISTG_W;
        const uint32_t* Alp = Ahp + IA_W;
        const uint32_t* Bhp = Ahp + 2 * IA_W;
        const uint32_t* Blp = Ahp + 3 * IA_W;

#pragma unroll
        for (int ksl = 0; ksl < 2; ++ksl) {       // two k32 slices
            const int kw0 = ksl * 8;
            uint32_t ah[2][4], al[2][4];
#pragma unroll
            for (int mf = 0; mf < 2; ++mf) {
                int r0 = wm * 32 + mf * 16 + (lane >> 2);
                int base = r0 * I_LDW + kw0 + (lane & 3);
                ah[mf][0] = Ahp[base];
                ah[mf][1] = Ahp[base + 8 * I_LDW];
                ah[mf][2] = Ahp[base + 4];
                ah[mf][3] = Ahp[base + 8 * I_LDW + 4];
                al[mf][0] = Alp[base];
                al[mf][1] = Alp[base + 8 * I_LDW];
                al[mf][2] = Alp[base + 4];
                al[mf][3] = Alp[base + 8 * I_LDW + 4];
            }
            uint32_t bh[4][2], bl[4][2];
#pragma unroll
            for (int nf = 0; nf < 4; ++nf) {
                int col = wn * 32 + nf * 8 + (lane >> 2);
                int base = col * I_LDW + kw0 + (lane & 3);
                bh[nf][0] = Bhp[base];
                bh[nf][1] = Bhp[base + 4];
                bl[nf][0] = Blp[base];
                bl[nf][1] = Blp[base + 4];
            }
#pragma unroll
            for (int mf = 0; mf < 2; ++mf)
#pragma unroll
                for (int nf = 0; nf < 4; ++nf) {
                    mma_s8(acc1[mf][nf], ah[mf], bh[nf]);
                    mma_s8(acc2[mf][nf], ah[mf], bl[nf]);
                    mma_s8(acc2[mf][nf], al[mf], bh[nf]);
                }
        }
        __syncthreads();
    }

    // Epilogue -> [B,H,S,HD], head = blockIdx.x
    const int h = blockIdx.x;
#pragma unroll
    for (int mf = 0; mf < 2; ++mf) {
#pragma unroll
        for (int nf = 0; nf < 4; ++nf) {
            int r0 = blockIdx.y * 128 + wm * 32 + mf * 16 + (lane >> 2);
            int r1 = r0 + 8;
            int cb = wn * 32 + nf * 8 + 2 * (lane & 3);       // 0..127 (=hd)
            int gc = h * 128 + cb;
            float s0 = sB[gc], s1 = sB[gc + 1];
            float fa0 = sA[r0], fa1 = sA[r1];
            float2 v0, v1;
            v0.x = (16384.f * (float)acc1[mf][nf][0] + 128.f * (float)acc2[mf][nf][0]) * fa0 * s0;
            v0.y = (16384.f * (float)acc1[mf][nf][1] + 128.f * (float)acc2[mf][nf][1]) * fa0 * s1;
            v1.x = (16384.f * (float)acc1[mf][nf][2] + 128.f * (float)acc2[mf][nf][2]) * fa1 * s0;
            v1.y = (16384.f * (float)acc1[mf][nf][3] + 128.f * (float)acc2[mf][nf][3]) * fa1 * s1;
            int b0 = r0 >> 11, ss0 = r0 & 2047;
            int b1 = r1 >> 11, ss1 = r1 & 2047;
            *(float2*)(C + (((size_t)b0 * Hx + h) * Sx + ss0) * HDx + cb) = v0;
            *(float2*)(C + (((size_t)b1 * Hx + h) * Sx + ss1) * HDx + cb) = v1;
        }
    }
}

// ---------------------------------------------------------------------------
// Split + transpose weights (bf16, for Wo): W[K,N] -> Tb/Ts[N, K/2].
// ---------------------------------------------------------------------------
__global__ __launch_bounds__(256)
void split_t_kernel(const float* __restrict__ W, uint32_t* __restrict__ Tb,
                    uint32_t* __restrict__ Ts) {
    __shared__ float t[32][33];
    int n0 = blockIdx.x * 32, k0 = blockIdx.y * 32;
    int tx = threadIdx.x & 31, ty = threadIdx.x >> 5;
#pragma unroll
    for (int i = 0; i < 4; ++i)
        t[ty + i * 8][tx] = W[(size_t)(k0 + ty + i * 8) * Dx + n0 + tx];
    __syncthreads();
    int kp = threadIdx.x & 15;
    int ny = threadIdx.x >> 4;
#pragma unroll
    for (int i = 0; i < 2; ++i) {
        int nl = ny + i * 16;
        uint32_t b, s;
        pack_split(t[2 * kp][nl], t[2 * kp + 1][nl], b, s);
        size_t o = (size_t)(n0 + nl) * (Dx / 2) + (k0 / 2) + kp;
        Tb[o] = b; Ts[o] = s;
    }
}

// ---------------------------------------------------------------------------
// BF16 GEMM for Wo (2-term split, 3 mma terms), 512 thr, 128x256, KT=64.
// ---------------------------------------------------------------------------
#define T_LDW 36
#define AT_W (128 * T_LDW)
#define BT_W (256 * T_LDW)
#define STG_W (2 * AT_W + 2 * BT_W)
#define GEMM_DYN (2 * STG_W * 4)

__global__ __launch_bounds__(512)
void bgemm256(const uint32_t* __restrict__ Abig, const uint32_t* __restrict__ Asml,
              const uint32_t* __restrict__ Wbig, const uint32_t* __restrict__ Wsml,
              float* __restrict__ C, int M, int N, int K) {
    extern __shared__ uint32_t sm[];
    const int tid  = threadIdx.x;
    const int lane = tid & 31;
    const int warp = tid >> 5;
    const int wm   = warp & 1;
    const int wn   = warp >> 1;
    const int KW = K / 2;
    const size_t aoff = (size_t)blockIdx.y * 128 * KW;
    const size_t boff = (size_t)blockIdx.x * 256 * KW;

    float acc[4][4][4];
#pragma unroll
    for (int i = 0; i < 4; ++i)
#pragma unroll
        for (int j = 0; j < 4; ++j)
#pragma unroll
            for (int t = 0; t < 4; ++t) acc[i][j][t] = 0.f;

    auto loadTiles = [&](int kt, int stg) {
        uint32_t* sb = sm + stg * STG_W;
        const int kw = kt / 2;
#pragma unroll
        for (int i = 0; i < 2; ++i) {
            int c = tid + 512 * i;
            int r = c >> 3, o = (c & 7) << 2;
            cpa16(sb + r * T_LDW + o, Abig + aoff + (size_t)r * KW + kw + o);
        }
#pragma unroll
        for (int i = 0; i < 2; ++i) {
            int c = tid + 512 * i;
            int r = c >> 3, o = (c & 7) << 2;
            cpa16(sb + AT_W + r * T_LDW + o, Asml + aoff + (size_t)r * KW + kw + o);
        }
#pragma unroll
        for (int i = 0; i < 4; ++i) {
            int c = tid + 512 * i;
            int r = c >> 3, o = (c & 7) << 2;
            cpa16(sb + 2 * AT_W + r * T_LDW + o, Wbig + boff + (size_t)r * KW + kw + o);
        }
#pragma unroll
        for (int i = 0; i < 4; ++i) {
            int c = tid + 512 * i;
            int r = c >> 3, o = (c & 7) << 2;
            cpa16(sb + 2 * AT_W + BT_W + r * T_LDW + o, Wsml + boff + (size_t)r * KW + kw + o);
        }
    };

    const int NT = K / 64;
    loadTiles(0, 0); cpa_commit();

    for (int it = 0; it < NT; ++it) {
        if (it + 1 < NT) {
            loadTiles((it + 1) * 64, (it + 1) & 1);
            cpa_commit();
            asm volatile("cp.async.wait_group 1;\n" ::: "memory");
        } else {
            asm volatile("cp.async.wait_group 0;\n" ::: "memory");
        }
        __syncthreads();

        const uint32_t* Ab = sm + (it & 1) * STG_W;
        const uint32_t* As = Ab + AT_W;
        const uint32_t* Bb = Ab + 2 * AT_W;
        const uint32_t* Bs = Bb + BT_W;

#pragma unroll
        for (int kk = 0; kk < 4; ++kk) {
            const int kw0 = kk * 8;
            uint32_t abig[4][4], asml[4][4];
#pragma unroll
            for (int mf = 0; mf < 4; ++mf) {
                int r0 = wm * 64 + mf * 16 + (lane >> 2);
                int base = r0 * T_LDW + kw0 + (lane & 3);
                abig[mf][0] = Ab[base];
                abig[mf][1] = Ab[base + 8 * T_LDW];
                abig[mf][2] = Ab[base + 4];
                abig[mf][3] = Ab[base + 8 * T_LDW + 4];
                asml[mf][0] = As[base];
                asml[mf][1] = As[base + 8 * T_LDW];
                asml[mf][2] = As[base + 4];
                asml[mf][3] = As[base + 8 * T_LDW + 4];
            }
            uint32_t bbig[4][2], bsml[4][2];
#pragma unroll
            for (int nf = 0; nf < 4; ++nf) {
                int col = wn * 32 + nf * 8 + (lane >> 2);
                int base = col * T_LDW + kw0 + (lane & 3);
                bbig[nf][0] = Bb[base];
                bbig[nf][1] = Bb[base + 4];
                bsml[nf][0] = Bs[base];
                bsml[nf][1] = Bs[base + 4];
            }
#pragma unroll
            for (int mf = 0; mf < 4; ++mf)
#pragma unroll
                for (int nf = 0; nf < 4; ++nf) {
                    mma_bf16(acc[mf][nf], asml[mf], bbig[nf]);
                    mma_bf16(acc[mf][nf], abig[mf], bsml[nf]);
                    mma_bf16(acc[mf][nf], abig[mf], bbig[nf]);
                }
        }
        __syncthreads();
    }

#pragma unroll
    for (int mf = 0; mf < 4; ++mf) {
#pragma unroll
        for (int nf = 0; nf < 4; ++nf) {
            int r0 = blockIdx.y * 128 + wm * 64 + mf * 16 + (lane >> 2);
            int r1 = r0 + 8;
            int cb = wn * 32 + nf * 8 + 2 * (lane & 3);
            float2 v0 = make_float2(acc[mf][nf][0], acc[mf][nf][1]);
            float2 v1 = make_float2(acc[mf][nf][2], acc[mf][nf][3]);
            *(float2*)(C + (size_t)r0 * N + blockIdx.x * 256 + cb) = v0;
            *(float2*)(C + (size_t)r1 * N + blockIdx.x * 256 + cb) = v1;
        }
    }
}

// ---------------------------------------------------------------------------
// RoPE + bf16-split q,k
// ---------------------------------------------------------------------------
__global__ __launch_bounds__(128)
void rope_split_kernel(const float* __restrict__ q, const float* __restrict__ k,
                       uint32_t* __restrict__ qb, uint32_t* __restrict__ qs,
                       uint32_t* __restrict__ kb, uint32_t* __restrict__ ks) {
    int row = blockIdx.x * 4 + (threadIdx.x >> 5);
    int j   = threadIdx.x & 31;
    int s   = row & (Sx - 1);
    float pos = (float)s;
    const float L = logf(10000.0f);
    float a0 = pos * expf(-L * (4.0f * j)        / 128.0f);
    float a1 = pos * expf(-L * (4.0f * j + 2.0f) / 128.0f);
    float c0, sn0, c1, sn1;
    sincosf(a0, &sn0, &c0);
    sincosf(a1, &sn1, &c1);

    const float* qr = q + (size_t)row * HDx;
    const float* kr = k + (size_t)row * HDx;
    size_t ob = (size_t)row * 64;

    {
        float x0 = qr[2*j], x1 = qr[2*j+1], y0 = qr[2*j+64], y1 = qr[2*j+65];
        uint32_t wb, ws;
        pack_split(x0 * c0 - y0 * sn0, x1 * c1 - y1 * sn1, wb, ws);
        qb[ob + j] = wb; qs[ob + j] = ws;
        pack_split(y0 * c0 + x0 * sn0, y1 * c1 + x1 * sn1, wb, ws);
        qb[ob + 32 + j] = wb; qs[ob + 32 + j] = ws;
    }
    {
        float x0 = kr[2*j], x1 = kr[2*j+1], y0 = kr[2*j+64], y1 = kr[2*j+65];
        uint32_t wb, ws;
        pack_split(x0 * c0 - y0 * sn0, x1 * c1 - y1 * sn1, wb, ws);
        kb[ob + j] = wb; ks[ob + j] = ws;
        pack_split(y0 * c0 + x0 * sn0, y1 * c1 + x1 * sn1, wb, ws);
        kb[ob + 32 + j] = wb; ks[ob + 32 + j] = ws;
    }
}

// ---------------------------------------------------------------------------
// V transpose+split
// ---------------------------------------------------------------------------
__global__ __launch_bounds__(256)
void vsplit_t_kernel(const float* __restrict__ v, uint32_t* __restrict__ Tb,
                     uint32_t* __restrict__ Ts) {
    __shared__ float t[32][33];
    int s0 = blockIdx.x * 32, d0 = blockIdx.y * 32, bh = blockIdx.z;
    int tx = threadIdx.x & 31, ty = threadIdx.x >> 5;
#pragma unroll
    for (int i = 0; i < 4; ++i) {
        int sl = ty + i * 8;
        t[sl][tx] = v[((size_t)bh * Sx + s0 + sl) * HDx + d0 + tx];
    }
    __syncthreads();
    int r  = threadIdx.x >> 3;
    int wq = threadIdx.x & 7;
    uint32_t b0, s0w, b1, s1w;
    pack_split(t[4*wq][r],   t[4*wq+1][r], b0, s0w);
    pack_split(t[4*wq+2][r], t[4*wq+3][r], b1, s1w);
    size_t o = ((size_t)bh * HDx + d0 + r) * (Sx / 2) + (s0 >> 1) + 2 * wq;
    Tb[o] = b0; Tb[o+1] = b1;
    Ts[o] = s0w; Ts[o+1] = s1w;
}

// ---------------------------------------------------------------------------
// Tensor-core flash attention (unchanged; writes split ctx into hb/hs)
// ---------------------------------------------------------------------------
#define FQ_LD 68
#define FV_LD 36
#define FOQS (128 * FQ_LD)
#define FSTG0 (2 * FOQS)
#define FK_W (64 * FQ_LD)
#define FV_W (128 * FV_LD)
#define FSTG_W (2 * FK_W + 2 * FV_W)
#define FLASH_DYN ((FSTG0 + 2 * FSTG_W) * 4)

__global__ __launch_bounds__(256)
void flash_tc(const uint32_t* __restrict__ Qb_, const uint32_t* __restrict__ Qs_,
              const uint32_t* __restrict__ Kb_, const uint32_t* __restrict__ Ks_,
              const uint32_t* __restrict__ Vb_, const uint32_t* __restrict__ Vs_,
              uint32_t* __restrict__ Ob_, uint32_t* __restrict__ Os_) {
    extern __shared__ uint32_t sw[];
    const int tid  = threadIdx.x;
    const int lane = tid & 31;
    const int warp = tid >> 5;
    const int qt   = 15 - blockIdx.x;
    const int bh   = blockIdx.y;

    const size_t qbase = ((size_t)bh * Sx + qt * 128) * 64;
#pragma unroll
    for (int i = 0; i < 8; ++i) {
        int c = tid + 256 * i;
        int r = c >> 4, w4 = (c & 15) * 4;
        cpa16(sw + r * FQ_LD + w4, Qb_ + qbase + r * 64 + w4);
        cpa16(sw + FOQS + r * FQ_LD + w4, Qs_ + qbase + r * 64 + w4);
    }

    auto loadKV = [&](int kt, int stg) {
        uint32_t* sb = sw + FSTG0 + stg * FSTG_W;
        const size_t kbase = ((size_t)bh * Sx + kt * 64) * 64;
#pragma unroll
        for (int i = 0; i < 4; ++i) {
            int c = tid + 256 * i;
            int r = c >> 4, w4 = (c & 15) * 4;
            cpa16(sb + r * FQ_LD + w4, Kb_ + kbase + r * 64 + w4);
            cpa16(sb + FK_W + r * FQ_LD + w4, Ks_ + kbase + r * 64 + w4);
        }
        const size_t vbase = (size_t)bh * HDx * (Sx / 2) + kt * 32;
#pragma unroll
        for (int i = 0; i < 4; ++i) {
            int c = tid + 256 * i;
            int d = c >> 3, w4 = (c & 7) * 4;
            cpa16(sb + 2 * FK_W + d * FV_LD + w4, Vb_ + vbase + (size_t)d * (Sx / 2) + w4);
            cpa16(sb + 2 * FK_W + FV_W + d * FV_LD + w4, Vs_ + vbase + (size_t)d * (Sx / 2) + w4);
        }
    };

    float o[16][4];
#pragma unroll
    for (int i = 0; i < 16; ++i)
#pragma unroll
        for (int t = 0; t < 4; ++t) o[i][t] = 0.f;
    float m0 = -INFINITY, m1 = -INFINITY, l0 = 0.f, l1 = 0.f;

    const float scale = 0.08838834764831845f;
    const int ktmax = 2 * qt + 1;
    loadKV(0, 0); cpa_commit();

    for (int kt = 0; kt <= ktmax; ++kt) {
        const int stg = kt & 1;
        if (kt < ktmax) {
            loadKV(kt + 1, stg ^ 1);
            cpa_commit();
            asm volatile("cp.async.wait_group 1;\n" ::: "memory");
        } else {
            asm volatile("cp.async.wait_group 0;\n" ::: "memory");
        }
        __syncthreads();

        const uint32_t* Kb = sw + FSTG0 + stg * FSTG_W;
        const uint32_t* Ks = Kb + FK_W;
        const uint32_t* Vb = Kb + 2 * FK_W;
        const uint32_t* Vs = Vb + FV_W;
        const uint32_t* Qbp = sw;
        const uint32_t* Qsp = sw + FOQS;

        float s[8][4];
#pragma unroll
        for (int nf = 0; nf < 8; ++nf)
#pragma unroll
            for (int t = 0; t < 4; ++t) s[nf][t] = 0.f;

#pragma unroll
        for (int ksl = 0; ksl < 8; ++ksl) {
            int ab = (warp * 16 + (lane >> 2)) * FQ_LD + ksl * 8 + (lane & 3);
            uint32_t qb[4] = {Qbp[ab], Qbp[ab + 8 * FQ_LD], Qbp[ab + 4], Qbp[ab + 8 * FQ_LD + 4]};
            uint32_t qs[4] = {Qsp[ab], Qsp[ab + 8 * FQ_LD], Qsp[ab + 4], Qsp[ab + 8 * FQ_LD + 4]};
#pragma unroll
            for (int nf = 0; nf < 8; ++nf) {
                int bb = (nf * 8 + (lane >> 2)) * FQ_LD + ksl * 8 + (lane & 3);
                uint32_t kb[2] = {Kb[bb], Kb[bb + 4]};
                uint32_t kk[2] = {Ks[bb], Ks[bb + 4]};
                mma_bf16(s[nf], qs, kb);
                mma_bf16(s[nf], qb, kk);
                mma_bf16(s[nf], qb, kb);
            }
        }

        const int rg0 = qt * 128 + warp * 16 + (lane >> 2);
        const int rg1 = rg0 + 8;
        const bool needmask = (kt >= 2 * qt);
#pragma unroll
        for (int nf = 0; nf < 8; ++nf) {
            int cb = kt * 64 + nf * 8 + 2 * (lane & 3);
#pragma unroll
            for (int t = 0; t < 4; ++t) {
                s[nf][t] *= scale;
                if (needmask) {
                    int col = cb + (t & 1);
                    int row = (t < 2) ? rg0 : rg1;
                    if (col > row) s[nf][t] = -1e30f;
                }
            }
        }

        float mx0 = -1e30f, mx1 = -1e30f;
#pragma unroll
        for (int nf = 0; nf < 8; ++nf) {
            mx0 = fmaxf(mx0, fmaxf(s[nf][0], s[nf][1]));
            mx1 = fmaxf(mx1, fmaxf(s[nf][2], s[nf][3]));
        }
        mx0 = fmaxf(mx0, __shfl_xor_sync(0xffffffffu, mx0, 1));
        mx0 = fmaxf(mx0, __shfl_xor_sync(0xffffffffu, mx0, 2));
        mx1 = fmaxf(mx1, __shfl_xor_sync(0xffffffffu, mx1, 1));
        mx1 = fmaxf(mx1, __shfl_xor_sync(0xffffffffu, mx1, 2));
        float mn0 = fmaxf(m0, mx0), mn1 = fmaxf(m1, mx1);
        float al0 = expf(m0 - mn0), al1 = expf(m1 - mn1);
        float ps0 = 0.f, ps1 = 0.f;
#pragma unroll
        for (int nf = 0; nf < 8; ++nf) {
            s[nf][0] = expf(s[nf][0] - mn0);
            s[nf][1] = expf(s[nf][1] - mn0);
            s[nf][2] = expf(s[nf][2] - mn1);
            s[nf][3] = expf(s[nf][3] - mn1);
            ps0 += s[nf][0] + s[nf][1];
            ps1 += s[nf][2] + s[nf][3];
        }
        ps0 += __shfl_xor_sync(0xffffffffu, ps0, 1);
        ps0 += __shfl_xor_sync(0xffffffffu, ps0, 2);
        ps1 += __shfl_xor_sync(0xffffffffu, ps1, 1);
        ps1 += __shfl_xor_sync(0xffffffffu, ps1, 2);
        l0 = l0 * al0 + ps0;
        l1 = l1 * al1 + ps1;
        m0 = mn0; m1 = mn1;
#pragma unroll
        for (int nf = 0; nf < 16; ++nf) {
            o[nf][0] *= al0; o[nf][1] *= al0;
            o[nf][2] *= al1; o[nf][3] *= al1;
        }

        uint32_t pb[4][4], pm[4][4];
#pragma unroll
        for (int j = 0; j < 4; ++j) {
            pack_split(s[2*j][0],   s[2*j][1],   pb[j][0], pm[j][0]);
            pack_split(s[2*j][2],   s[2*j][3],   pb[j][1], pm[j][1]);
            pack_split(s[2*j+1][0], s[2*j+1][1], pb[j][2], pm[j][2]);
            pack_split(s[2*j+1][2], s[2*j+1][3], pb[j][3], pm[j][3]);
        }

#pragma unroll
        for (int j = 0; j < 4; ++j) {
#pragma unroll
            for (int nf = 0; nf < 16; ++nf) {
                int vb = (nf * 8 + (lane >> 2)) * FV_LD + j * 8 + (lane & 3);
                uint32_t vbig[2] = {Vb[vb], Vb[vb + 4]};
                uint32_t vsml[2] = {Vs[vb], Vs[vb + 4]};
                mma_bf16(o[nf], pm[j], vbig);
                mma_bf16(o[nf], pb[j], vsml);
                mma_bf16(o[nf], pb[j], vbig);
            }
        }
        __syncthreads();
    }

    const int b = bh >> 4;
    const int h = bh & 15;
    const float inv0 = 1.0f / l0;
    const float inv1 = 1.0f / l1;
    const int r0g = qt * 128 + warp * 16 + (lane >> 2);
    const int r1g = r0g + 8;
    const size_t row0 = ((size_t)b * Sx + r0g) * 1024 + h * 64;
    const size_t row1 = ((size_t)b * Sx + r1g) * 1024 + h * 64;
#pragma unroll
    for (int nf = 0; nf < 16; ++nf) {
        int dw = (nf * 8 + 2 * (lane & 3)) >> 1;
        uint32_t wb, ws;
        pack_split(o[nf][0] * inv0, o[nf][1] * inv0, wb, ws);
        Ob_[row0 + dw] = wb; Os_[row0 + dw] = ws;
        pack_split(o[nf][2] * inv1, o[nf][3] * inv1, wb, ws);
        Ob_[row1 + dw] = wb; Os_[row1 + dw] = ws;
    }
}

// ---------------------------------------------------------------------------
// Launch
// ---------------------------------------------------------------------------
extern "C" void kernel_launch(void* const* d_in, const int* in_sizes, int n_in,
                              void* d_out, int out_size) {
    const float* hidden = (const float*)d_in[0];
    const float* Wq = (const float*)d_in[3];
    const float* Wk = (const float*)d_in[4];
    const float* Wv = (const float*)d_in[5];
    const float* Wo = (const float*)d_in[6];

    float *q, *k, *v;
    uint32_t *hb, *hs, *wob, *wos;
    uint32_t *a8h, *a8l, *wq8h, *wq8l, *wk8h, *wk8l, *wv8h, *wv8l;
    float *sA, *sq, *sk, *sv;
    uint32_t *qsb, *qss, *ksb, *kss, *vtb, *vts;
    cudaGetSymbolAddress((void**)&q,    g_q);
    cudaGetSymbolAddress((void**)&k,    g_k);
    cudaGetSymbolAddress((void**)&v,    g_v);
    cudaGetSymbolAddress((void**)&hb,   g_hb);
    cudaGetSymbolAddress((void**)&hs,   g_hs);
    cudaGetSymbolAddress((void**)&wob,  g_wob);
    cudaGetSymbolAddress((void**)&wos,  g_wos);
    cudaGetSymbolAddress((void**)&a8h,  g_a8h);
    cudaGetSymbolAddress((void**)&a8l,  g_a8l);
    cudaGetSymbolAddress((void**)&wq8h, g_wq8h);
    cudaGetSymbolAddress((void**)&wq8l, g_wq8l);
    cudaGetSymbolAddress((void**)&wk8h, g_wk8h);
    cudaGetSymbolAddress((void**)&wk8l, g_wk8l);
    cudaGetSymbolAddress((void**)&wv8h, g_wv8h);
    cudaGetSymbolAddress((void**)&wv8l, g_wv8l);
    cudaGetSymbolAddress((void**)&sA,   g_sA);
    cudaGetSymbolAddress((void**)&sq,   g_sq);
    cudaGetSymbolAddress((void**)&sk,   g_sk);
    cudaGetSymbolAddress((void**)&sv,   g_sv);
    cudaGetSymbolAddress((void**)&qsb,  g_qsb);
    cudaGetSymbolAddress((void**)&qss,  g_qss);
    cudaGetSymbolAddress((void**)&ksb,  g_ksb);
    cudaGetSymbolAddress((void**)&kss,  g_kss);
    cudaGetSymbolAddress((void**)&vtb,  g_vtb);
    cudaGetSymbolAddress((void**)&vts,  g_vts);

    cudaFuncSetAttribute(igemm128, cudaFuncAttributeMaxDynamicSharedMemorySize, IGEMM_DYN);
    cudaFuncSetAttribute(bgemm256, cudaFuncAttributeMaxDynamicSharedMemorySize, GEMM_DYN);
    cudaFuncSetAttribute(flash_tc, cudaFuncAttributeMaxDynamicSharedMemorySize, FLASH_DYN);

    dim3 igrid(Dx / 128, Mx / 128);       // (16, 32)
    dim3 ggrid(Dx / 256, Mx / 128);       // (8, 32)
    dim3 tr_grid(Dx / 32, Dx / 32);

    // idx0-4: quantization prep; idx5 = first igemm (profiled by ncu -s 5 -c 1)
    quant_rows<<<Mx, 256>>>(hidden, a8h, a8l, sA);
    colmax_scale<<<Dx / 256, 256>>>(Wq, sq);
    quantT8<<<tr_grid, 256>>>(Wq, sq, wq8h, wq8l);
    colmax_scale<<<Dx / 256, 256>>>(Wk, sk);
    quantT8<<<tr_grid, 256>>>(Wk, sk, wk8h, wk8l);
    igemm128<<<igrid, 512, IGEMM_DYN>>>(a8h, a8l, wq8h, wq8l, sA, sq, q);
    colmax_scale<<<Dx / 256, 256>>>(Wv, sv);
    quantT8<<<tr_grid, 256>>>(Wv, sv, wv8h, wv8l);
    igemm128<<<igrid, 512, IGEMM_DYN>>>(a8h, a8l, wk8h, wk8l, sA, sk, k);
    igemm128<<<igrid, 512, IGEMM_DYN>>>(a8h, a8l, wv8h, wv8l, sA, sv, v);

    rope_split_kernel<<<(32 * Sx) / 4, 128>>>(q, k, qsb, qss, ksb, kss);
    vsplit_t_kernel<<<dim3(Sx / 32, HDx / 32, 32), 256>>>(v, vtb, vts);
    split_t_kernel<<<tr_grid, 256>>>(Wo, wob, wos);

    flash_tc<<<dim3(16, 32), 256, FLASH_DYN>>>(qsb, qss, ksb, kss, vtb, vts, hb, hs);

    bgemm256<<<ggrid, 512, GEMM_DYN>>>(hb, hs, wob, wos, (float*)d_out, Mx, Dx, Dx);
}

// round 14
// speedup vs baseline: 2.0115x; 2.0115x over previous
#include <cuda_runtime.h>
#include <cuda_bf16.h>
#include <math.h>
#include <stdint.h>

// Problem constants
#define Bx 2
#define Sx 2048
#define Dx 2048
#define Hx 16
#define HDx 128
#define Mx (Bx*Sx)   // 4096

// Scratch (device globals; no allocation allowed)
__device__ float g_q[(size_t)Mx * Dx];
__device__ float g_k[(size_t)Mx * Dx];
__device__ float g_v[(size_t)Mx * Dx];
// bf16 2-term split buffers (packed pairs along K).
__device__ uint32_t g_hb[(size_t)Mx * Dx / 2];
__device__ uint32_t g_hs[(size_t)Mx * Dx / 2];
// Concatenated QKV weight splits: rows [0,2048)=Wq^T, [2048,4096)=Wk^T, [4096,6144)=Wv^T
__device__ uint32_t g_w3b[(size_t)3 * Dx * Dx / 2];
__device__ uint32_t g_w3s[(size_t)3 * Dx * Dx / 2];
__device__ uint32_t g_wob[(size_t)Dx * Dx / 2];
__device__ uint32_t g_wos[(size_t)Dx * Dx / 2];
// Flash operands: roped q,k split pairs [bh][s][64 words]; V^T split [bh][d][1024 words]
__device__ uint32_t g_qsb[(size_t)32 * 2048 * 64];
__device__ uint32_t g_qss[(size_t)32 * 2048 * 64];
__device__ uint32_t g_ksb[(size_t)32 * 2048 * 64];
__device__ uint32_t g_kss[(size_t)32 * 2048 * 64];
__device__ uint32_t g_vtb[(size_t)32 * 128 * 1024];
__device__ uint32_t g_vts[(size_t)32 * 128 * 1024];

// ---------------------------------------------------------------------------
// Helpers
// ---------------------------------------------------------------------------
__device__ __forceinline__ void cpa16(void* smem, const void* gmem) {
    uint32_t s = (uint32_t)__cvta_generic_to_shared(smem);
    asm volatile("cp.async.cg.shared.global [%0], [%1], 16;\n" :: "r"(s), "l"(gmem));
}
__device__ __forceinline__ void cpa_commit() {
    asm volatile("cp.async.commit_group;\n");
}
__device__ __forceinline__ uint16_t f2bf(float x) {
    __nv_bfloat16 h = __float2bfloat16_rn(x);
    return *(uint16_t*)&h;
}
__device__ __forceinline__ float bf2f(uint16_t b) {
    __nv_bfloat16 h = *(__nv_bfloat16*)&b;
    return __bfloat162float(h);
}
__device__ __forceinline__ void split_bf(float x, uint16_t& big, uint16_t& sml) {
    big = f2bf(x);
    sml = f2bf(x - bf2f(big));
}
__device__ __forceinline__ void pack_split(float x, float y, uint32_t& bb, uint32_t& ss) {
    uint16_t bx, sx, by, sy;
    split_bf(x, bx, sx); split_bf(y, by, sy);
    bb = (uint32_t)bx | ((uint32_t)by << 16);
    ss = (uint32_t)sx | ((uint32_t)sy << 16);
}
__device__ __forceinline__ void mma_bf16(float c[4], const uint32_t a[4], const uint32_t b[2]) {
    asm volatile(
        "mma.sync.aligned.m16n8k16.row.col.f32.bf16.bf16.f32 "
        "{%0,%1,%2,%3},{%4,%5,%6,%7},{%8,%9},{%0,%1,%2,%3};\n"
        : "+f"(c[0]), "+f"(c[1]), "+f"(c[2]), "+f"(c[3])
        : "r"(a[0]), "r"(a[1]), "r"(a[2]), "r"(a[3]), "r"(b[0]), "r"(b[1]));
}

// ---------------------------------------------------------------------------
// Split prep (row-major)
// ---------------------------------------------------------------------------
__global__ __launch_bounds__(256)
void split_kernel(const float* __restrict__ X, uint32_t* __restrict__ Bg,
                  uint32_t* __restrict__ Sm, int n4) {
    int i = blockIdx.x * 256 + threadIdx.x;
    if (i >= n4) return;
    float4 x = ((const float4*)X)[i];
    uint2 b, s;
    pack_split(x.x, x.y, b.x, s.x);
    pack_split(x.z, x.w, b.y, s.y);
    ((uint2*)Bg)[i] = b;
    ((uint2*)Sm)[i] = s;
}

// ---------------------------------------------------------------------------
// Split + transpose weights: W[K,N] fp32 -> Tb/Ts[N, K/2] packed bf16 pairs.
// ---------------------------------------------------------------------------
__global__ __launch_bounds__(256)
void split_t_kernel(const float* __restrict__ W, uint32_t* __restrict__ Tb,
                    uint32_t* __restrict__ Ts) {
    __shared__ float t[32][33];
    int n0 = blockIdx.x * 32, k0 = blockIdx.y * 32;
    int tx = threadIdx.x & 31, ty = threadIdx.x >> 5;
#pragma unroll
    for (int i = 0; i < 4; ++i)
        t[ty + i * 8][tx] = W[(size_t)(k0 + ty + i * 8) * Dx + n0 + tx];
    __syncthreads();
    int kp = threadIdx.x & 15;
    int ny = threadIdx.x >> 4;
#pragma unroll
    for (int i = 0; i < 2; ++i) {
        int nl = ny + i * 16;
        uint32_t b, s;
        pack_split(t[2 * kp][nl], t[2 * kp + 1][nl], b, s);
        size_t o = (size_t)(n0 + nl) * (Dx / 2) + (k0 / 2) + kp;
        Tb[o] = b; Ts[o] = s;
    }
}

// ---------------------------------------------------------------------------
// BF16 mma.sync GEMM (2-term split, 3 mma terms), 512 thr, 128x256 tile, KT=64.
// A row-major [M,K]; B K-major [N,K] packed bf16 pairs. fp32 out.
// OUT_MODE 0: row-major [M,2048] into Cq (grid.x in [0,8)).
// OUT_MODE 1: fused QKV — B is concatenated [6144,K]; grid.x in [0,24);
//             output buffer Cq/Ck/Cv chosen by blockIdx.x>>3; [B,H,S,HD].
// ---------------------------------------------------------------------------
#define T_LDW 36
#define AT_W (128 * T_LDW)
#define BT_W (256 * T_LDW)
#define STG_W (2 * AT_W + 2 * BT_W)
#define GEMM_DYN (2 * STG_W * 4)

template <int OUT_MODE>
__global__ __launch_bounds__(512)
void bgemm256(const uint32_t* __restrict__ Abig, const uint32_t* __restrict__ Asml,
              const uint32_t* __restrict__ Wbig, const uint32_t* __restrict__ Wsml,
              float* __restrict__ Cq, float* __restrict__ Ck, float* __restrict__ Cv) {
    extern __shared__ uint32_t sm[];
    const int tid  = threadIdx.x;
    const int lane = tid & 31;
    const int warp = tid >> 5;
    const int wm   = warp & 1;
    const int wn   = warp >> 1;
    const int KW = Dx / 2;
    const size_t aoff = (size_t)blockIdx.y * 128 * KW;
    const size_t boff = (size_t)blockIdx.x * 256 * KW;

    float acc[4][4][4];
#pragma unroll
    for (int i = 0; i < 4; ++i)
#pragma unroll
        for (int j = 0; j < 4; ++j)
#pragma unroll
            for (int t = 0; t < 4; ++t) acc[i][j][t] = 0.f;

    auto loadTiles = [&](int kt, int stg) {
        uint32_t* sb = sm + stg * STG_W;
        const int kw = kt / 2;
#pragma unroll
        for (int i = 0; i < 2; ++i) {
            int c = tid + 512 * i;
            int r = c >> 3, o = (c & 7) << 2;
            cpa16(sb + r * T_LDW + o, Abig + aoff + (size_t)r * KW + kw + o);
        }
#pragma unroll
        for (int i = 0; i < 2; ++i) {
            int c = tid + 512 * i;
            int r = c >> 3, o = (c & 7) << 2;
            cpa16(sb + AT_W + r * T_LDW + o, Asml + aoff + (size_t)r * KW + kw + o);
        }
#pragma unroll
        for (int i = 0; i < 4; ++i) {
            int c = tid + 512 * i;
            int r = c >> 3, o = (c & 7) << 2;
            cpa16(sb + 2 * AT_W + r * T_LDW + o, Wbig + boff + (size_t)r * KW + kw + o);
        }
#pragma unroll
        for (int i = 0; i < 4; ++i) {
            int c = tid + 512 * i;
            int r = c >> 3, o = (c & 7) << 2;
            cpa16(sb + 2 * AT_W + BT_W + r * T_LDW + o, Wsml + boff + (size_t)r * KW + kw + o);
        }
    };

    const int NT = Dx / 64;
    loadTiles(0, 0); cpa_commit();

    for (int it = 0; it < NT; ++it) {
        if (it + 1 < NT) {
            loadTiles((it + 1) * 64, (it + 1) & 1);
            cpa_commit();
            asm volatile("cp.async.wait_group 1;\n" ::: "memory");
        } else {
            asm volatile("cp.async.wait_group 0;\n" ::: "memory");
        }
        __syncthreads();

        const uint32_t* Ab = sm + (it & 1) * STG_W;
        const uint32_t* As = Ab + AT_W;
        const uint32_t* Bb = Ab + 2 * AT_W;
        const uint32_t* Bs = Bb + BT_W;

#pragma unroll
        for (int kk = 0; kk < 4; ++kk) {
            const int kw0 = kk * 8;
            uint32_t abig[4][4], asml[4][4];
#pragma unroll
            for (int mf = 0; mf < 4; ++mf) {
                int r0 = wm * 64 + mf * 16 + (lane >> 2);
                int base = r0 * T_LDW + kw0 + (lane & 3);
                abig[mf][0] = Ab[base];
                abig[mf][1] = Ab[base + 8 * T_LDW];
                abig[mf][2] = Ab[base + 4];
                abig[mf][3] = Ab[base + 8 * T_LDW + 4];
                asml[mf][0] = As[base];
                asml[mf][1] = As[base + 8 * T_LDW];
                asml[mf][2] = As[base + 4];
                asml[mf][3] = As[base + 8 * T_LDW + 4];
            }
            uint32_t bbig[4][2], bsml[4][2];
#pragma unroll
            for (int nf = 0; nf < 4; ++nf) {
                int col = wn * 32 + nf * 8 + (lane >> 2);
                int base = col * T_LDW + kw0 + (lane & 3);
                bbig[nf][0] = Bb[base];
                bbig[nf][1] = Bb[base + 4];
                bsml[nf][0] = Bs[base];
                bsml[nf][1] = Bs[base + 4];
            }
#pragma unroll
            for (int mf = 0; mf < 4; ++mf)
#pragma unroll
                for (int nf = 0; nf < 4; ++nf) {
                    mma_bf16(acc[mf][nf], asml[mf], bbig[nf]);
                    mma_bf16(acc[mf][nf], abig[mf], bsml[nf]);
                    mma_bf16(acc[mf][nf], abig[mf], bbig[nf]);
                }
        }
        __syncthreads();
    }

    // Epilogue
    float* C = Cq;
    int bxl = blockIdx.x;
    if (OUT_MODE == 1) {
        const int widx = blockIdx.x >> 3;
        C = (widx == 0) ? Cq : (widx == 1) ? Ck : Cv;
        bxl = blockIdx.x & 7;
    }
#pragma unroll
    for (int mf = 0; mf < 4; ++mf) {
#pragma unroll
        for (int nf = 0; nf < 4; ++nf) {
            int r0 = blockIdx.y * 128 + wm * 64 + mf * 16 + (lane >> 2);
            int r1 = r0 + 8;
            int cb = wn * 32 + nf * 8 + 2 * (lane & 3);
            float2 v0 = make_float2(acc[mf][nf][0], acc[mf][nf][1]);
            float2 v1 = make_float2(acc[mf][nf][2], acc[mf][nf][3]);
            if (OUT_MODE == 0) {
                *(float2*)(C + (size_t)r0 * Dx + bxl * 256 + cb) = v0;
                *(float2*)(C + (size_t)r1 * Dx + bxl * 256 + cb) = v1;
            } else {
                int h  = bxl * 2 + (cb >> 7);
                int hd = cb & 127;
                int b0 = r0 >> 11, s0 = r0 & 2047;
                int b1 = r1 >> 11, s1 = r1 & 2047;
                *(float2*)(C + (((size_t)b0 * Hx + h) * Sx + s0) * HDx + hd) = v0;
                *(float2*)(C + (((size_t)b1 * Hx + h) * Sx + s1) * HDx + hd) = v1;
            }
        }
    }
}

// ---------------------------------------------------------------------------
// RoPE + bf16-split: reads fp32 q,k [bh][s][128], writes split pairs
// [bh*2048+s][64 words].
// ---------------------------------------------------------------------------
__global__ __launch_bounds__(128)
void rope_split_kernel(const float* __restrict__ q, const float* __restrict__ k,
                       uint32_t* __restrict__ qb, uint32_t* __restrict__ qs,
                       uint32_t* __restrict__ kb, uint32_t* __restrict__ ks) {
    int row = blockIdx.x * 4 + (threadIdx.x >> 5);
    int j   = threadIdx.x & 31;
    int s   = row & (Sx - 1);
    float pos = (float)s;
    const float L = logf(10000.0f);
    float a0 = pos * expf(-L * (4.0f * j)        / 128.0f);
    float a1 = pos * expf(-L * (4.0f * j + 2.0f) / 128.0f);
    float c0, sn0, c1, sn1;
    sincosf(a0, &sn0, &c0);
    sincosf(a1, &sn1, &c1);

    const float* qr = q + (size_t)row * HDx;
    const float* kr = k + (size_t)row * HDx;
    size_t ob = (size_t)row * 64;

    {
        float x0 = qr[2*j], x1 = qr[2*j+1], y0 = qr[2*j+64], y1 = qr[2*j+65];
        uint32_t wb, ws;
        pack_split(x0 * c0 - y0 * sn0, x1 * c1 - y1 * sn1, wb, ws);
        qb[ob + j] = wb; qs[ob + j] = ws;
        pack_split(y0 * c0 + x0 * sn0, y1 * c1 + x1 * sn1, wb, ws);
        qb[ob + 32 + j] = wb; qs[ob + 32 + j] = ws;
    }
    {
        float x0 = kr[2*j], x1 = kr[2*j+1], y0 = kr[2*j+64], y1 = kr[2*j+65];
        uint32_t wb, ws;
        pack_split(x0 * c0 - y0 * sn0, x1 * c1 - y1 * sn1, wb, ws);
        kb[ob + j] = wb; ks[ob + j] = ws;
        pack_split(y0 * c0 + x0 * sn0, y1 * c1 + x1 * sn1, wb, ws);
        kb[ob + 32 + j] = wb; ks[ob + 32 + j] = ws;
    }
}

// ---------------------------------------------------------------------------
// V transpose+split: v fp32 [bh][s][128] -> vtb/vts [bh][d][1024 words]
// ---------------------------------------------------------------------------
__global__ __launch_bounds__(256)
void vsplit_t_kernel(const float* __restrict__ v, uint32_t* __restrict__ Tb,
                     uint32_t* __restrict__ Ts) {
    __shared__ float t[32][33];
    int s0 = blockIdx.x * 32, d0 = blockIdx.y * 32, bh = blockIdx.z;
    int tx = threadIdx.x & 31, ty = threadIdx.x >> 5;
#pragma unroll
    for (int i = 0; i < 4; ++i) {
        int sl = ty + i * 8;
        t[sl][tx] = v[((size_t)bh * Sx + s0 + sl) * HDx + d0 + tx];
    }
    __syncthreads();
    int r  = threadIdx.x >> 3;
    int wq = threadIdx.x & 7;
    uint32_t b0, s0w, b1, s1w;
    pack_split(t[4*wq][r],   t[4*wq+1][r], b0, s0w);
    pack_split(t[4*wq+2][r], t[4*wq+3][r], b1, s1w);
    size_t o = ((size_t)bh * HDx + d0 + r) * (Sx / 2) + (s0 >> 1) + 2 * wq;
    Tb[o] = b0; Tb[o+1] = b1;
    Ts[o] = s0w; Ts[o+1] = s1w;
}

// ---------------------------------------------------------------------------
// Tensor-core flash attention (bf16 2-term split, fp32 softmax, causal).
// Writes ctx as split bf16 pairs into hb/hs (row [b*S+s], word h*64+d/2).
// ---------------------------------------------------------------------------
#define FQ_LD 68
#define FV_LD 36
#define FOQS (128 * FQ_LD)
#define FSTG0 (2 * FOQS)
#define FK_W (64 * FQ_LD)
#define FV_W (128 * FV_LD)
#define FSTG_W (2 * FK_W + 2 * FV_W)
#define FLASH_DYN ((FSTG0 + 2 * FSTG_W) * 4)

__global__ __launch_bounds__(256)
void flash_tc(const uint32_t* __restrict__ Qb_, const uint32_t* __restrict__ Qs_,
              const uint32_t* __restrict__ Kb_, const uint32_t* __restrict__ Ks_,
              const uint32_t* __restrict__ Vb_, const uint32_t* __restrict__ Vs_,
              uint32_t* __restrict__ Ob_, uint32_t* __restrict__ Os_) {
    extern __shared__ uint32_t sw[];
    const int tid  = threadIdx.x;
    const int lane = tid & 31;
    const int warp = tid >> 5;
    const int qt   = 15 - blockIdx.x;
    const int bh   = blockIdx.y;

    const size_t qbase = ((size_t)bh * Sx + qt * 128) * 64;
#pragma unroll
    for (int i = 0; i < 8; ++i) {
        int c = tid + 256 * i;
        int r = c >> 4, w4 = (c & 15) * 4;
        cpa16(sw + r * FQ_LD + w4, Qb_ + qbase + r * 64 + w4);
        cpa16(sw + FOQS + r * FQ_LD + w4, Qs_ + qbase + r * 64 + w4);
    }

    auto loadKV = [&](int kt, int stg) {
        uint32_t* sb = sw + FSTG0 + stg * FSTG_W;
        const size_t kbase = ((size_t)bh * Sx + kt * 64) * 64;
#pragma unroll
        for (int i = 0; i < 4; ++i) {
            int c = tid + 256 * i;
            int r = c >> 4, w4 = (c & 15) * 4;
            cpa16(sb + r * FQ_LD + w4, Kb_ + kbase + r * 64 + w4);
            cpa16(sb + FK_W + r * FQ_LD + w4, Ks_ + kbase + r * 64 + w4);
        }
        const size_t vbase = (size_t)bh * HDx * (Sx / 2) + kt * 32;
#pragma unroll
        for (int i = 0; i < 4; ++i) {
            int c = tid + 256 * i;
            int d = c >> 3, w4 = (c & 7) * 4;
            cpa16(sb + 2 * FK_W + d * FV_LD + w4, Vb_ + vbase + (size_t)d * (Sx / 2) + w4);
            cpa16(sb + 2 * FK_W + FV_W + d * FV_LD + w4, Vs_ + vbase + (size_t)d * (Sx / 2) + w4);
        }
    };

    float o[16][4];
#pragma unroll
    for (int i = 0; i < 16; ++i)
#pragma unroll
        for (int t = 0; t < 4; ++t) o[i][t] = 0.f;
    float m0 = -INFINITY, m1 = -INFINITY, l0 = 0.f, l1 = 0.f;

    const float scale = 0.08838834764831845f;
    const int ktmax = 2 * qt + 1;
    loadKV(0, 0); cpa_commit();

    for (int kt = 0; kt <= ktmax; ++kt) {
        const int stg = kt & 1;
        if (kt < ktmax) {
            loadKV(kt + 1, stg ^ 1);
            cpa_commit();
            asm volatile("cp.async.wait_group 1;\n" ::: "memory");
        } else {
            asm volatile("cp.async.wait_group 0;\n" ::: "memory");
        }
        __syncthreads();

        const uint32_t* Kb = sw + FSTG0 + stg * FSTG_W;
        const uint32_t* Ks = Kb + FK_W;
        const uint32_t* Vb = Kb + 2 * FK_W;
        const uint32_t* Vs = Vb + FV_W;
        const uint32_t* Qbp = sw;
        const uint32_t* Qsp = sw + FOQS;

        float s[8][4];
#pragma unroll
        for (int nf = 0; nf < 8; ++nf)
#pragma unroll
            for (int t = 0; t < 4; ++t) s[nf][t] = 0.f;

#pragma unroll
        for (int ksl = 0; ksl < 8; ++ksl) {
            int ab = (warp * 16 + (lane >> 2)) * FQ_LD + ksl * 8 + (lane & 3);
            uint32_t qb[4] = {Qbp[ab], Qbp[ab + 8 * FQ_LD], Qbp[ab + 4], Qbp[ab + 8 * FQ_LD + 4]};
            uint32_t qs[4] = {Qsp[ab], Qsp[ab + 8 * FQ_LD], Qsp[ab + 4], Qsp[ab + 8 * FQ_LD + 4]};
#pragma unroll
            for (int nf = 0; nf < 8; ++nf) {
                int bb = (nf * 8 + (lane >> 2)) * FQ_LD + ksl * 8 + (lane & 3);
                uint32_t kb[2] = {Kb[bb], Kb[bb + 4]};
                uint32_t kk[2] = {Ks[bb], Ks[bb + 4]};
                mma_bf16(s[nf], qs, kb);
                mma_bf16(s[nf], qb, kk);
                mma_bf16(s[nf], qb, kb);
            }
        }

        const int rg0 = qt * 128 + warp * 16 + (lane >> 2);
        const int rg1 = rg0 + 8;
        const bool needmask = (kt >= 2 * qt);
#pragma unroll
        for (int nf = 0; nf < 8; ++nf) {
            int cb = kt * 64 + nf * 8 + 2 * (lane & 3);
#pragma unroll
            for (int t = 0; t < 4; ++t) {
                s[nf][t] *= scale;
                if (needmask) {
                    int col = cb + (t & 1);
                    int row = (t < 2) ? rg0 : rg1;
                    if (col > row) s[nf][t] = -1e30f;
                }
            }
        }

        float mx0 = -1e30f, mx1 = -1e30f;
#pragma unroll
        for (int nf = 0; nf < 8; ++nf) {
            mx0 = fmaxf(mx0, fmaxf(s[nf][0], s[nf][1]));
            mx1 = fmaxf(mx1, fmaxf(s[nf][2], s[nf][3]));
        }
        mx0 = fmaxf(mx0, __shfl_xor_sync(0xffffffffu, mx0, 1));
        mx0 = fmaxf(mx0, __shfl_xor_sync(0xffffffffu, mx0, 2));
        mx1 = fmaxf(mx1, __shfl_xor_sync(0xffffffffu, mx1, 1));
        mx1 = fmaxf(mx1, __shfl_xor_sync(0xffffffffu, mx1, 2));
        float mn0 = fmaxf(m0, mx0), mn1 = fmaxf(m1, mx1);
        float al0 = expf(m0 - mn0), al1 = expf(m1 - mn1);
        float ps0 = 0.f, ps1 = 0.f;
#pragma unroll
        for (int nf = 0; nf < 8; ++nf) {
            s[nf][0] = expf(s[nf][0] - mn0);
            s[nf][1] = expf(s[nf][1] - mn0);
            s[nf][2] = expf(s[nf][2] - mn1);
            s[nf][3] = expf(s[nf][3] - mn1);
            ps0 += s[nf][0] + s[nf][1];
            ps1 += s[nf][2] + s[nf][3];
        }
        ps0 += __shfl_xor_sync(0xffffffffu, ps0, 1);
        ps0 += __shfl_xor_sync(0xffffffffu, ps0, 2);
        ps1 += __shfl_xor_sync(0xffffffffu, ps1, 1);
        ps1 += __shfl_xor_sync(0xffffffffu, ps1, 2);
        l0 = l0 * al0 + ps0;
        l1 = l1 * al1 + ps1;
        m0 = mn0; m1 = mn1;
#pragma unroll
        for (int nf = 0; nf < 16; ++nf) {
            o[nf][0] *= al0; o[nf][1] *= al0;
            o[nf][2] *= al1; o[nf][3] *= al1;
        }

        uint32_t pb[4][4], pm[4][4];
#pragma unroll
        for (int j = 0; j < 4; ++j) {
            pack_split(s[2*j][0],   s[2*j][1],   pb[j][0], pm[j][0]);
            pack_split(s[2*j][2],   s[2*j][3],   pb[j][1], pm[j][1]);
            pack_split(s[2*j+1][0], s[2*j+1][1], pb[j][2], pm[j][2]);
            pack_split(s[2*j+1][2], s[2*j+1][3], pb[j][3], pm[j][3]);
        }

#pragma unroll
        for (int j = 0; j < 4; ++j) {
#pragma unroll
            for (int nf = 0; nf < 16; ++nf) {
                int vb = (nf * 8 + (lane >> 2)) * FV_LD + j * 8 + (lane & 3);
                uint32_t vbig[2] = {Vb[vb], Vb[vb + 4]};
                uint32_t vsml[2] = {Vs[vb], Vs[vb + 4]};
                mma_bf16(o[nf], pm[j], vbig);
                mma_bf16(o[nf], pb[j], vsml);
                mma_bf16(o[nf], pb[j], vbig);
            }
        }
        __syncthreads();
    }

    const int b = bh >> 4;
    const int h = bh & 15;
    const float inv0 = 1.0f / l0;
    const float inv1 = 1.0f / l1;
    const int r0g = qt * 128 + warp * 16 + (lane >> 2);
    const int r1g = r0g + 8;
    const size_t row0 = ((size_t)b * Sx + r0g) * 1024 + h * 64;
    const size_t row1 = ((size_t)b * Sx + r1g) * 1024 + h * 64;
#pragma unroll
    for (int nf = 0; nf < 16; ++nf) {
        int dw = (nf * 8 + 2 * (lane & 3)) >> 1;
        uint32_t wb, ws;
        pack_split(o[nf][0] * inv0, o[nf][1] * inv0, wb, ws);
        Ob_[row0 + dw] = wb; Os_[row0 + dw] = ws;
        pack_split(o[nf][2] * inv1, o[nf][3] * inv1, wb, ws);
        Ob_[row1 + dw] = wb; Os_[row1 + dw] = ws;
    }
}

// ---------------------------------------------------------------------------
// Launch
// ---------------------------------------------------------------------------
extern "C" void kernel_launch(void* const* d_in, const int* in_sizes, int n_in,
                              void* d_out, int out_size) {
    const float* hidden = (const float*)d_in[0];
    const float* Wq = (const float*)d_in[3];
    const float* Wk = (const float*)d_in[4];
    const float* Wv = (const float*)d_in[5];
    const float* Wo = (const float*)d_in[6];

    float *q, *k, *v;
    uint32_t *hb, *hs, *w3b, *w3s, *wob, *wos;
    uint32_t *qsb, *qss, *ksb, *kss, *vtb, *vts;
    cudaGetSymbolAddress((void**)&q,   g_q);
    cudaGetSymbolAddress((void**)&k,   g_k);
    cudaGetSymbolAddress((void**)&v,   g_v);
    cudaGetSymbolAddress((void**)&hb,  g_hb);
    cudaGetSymbolAddress((void**)&hs,  g_hs);
    cudaGetSymbolAddress((void**)&w3b, g_w3b);
    cudaGetSymbolAddress((void**)&w3s, g_w3s);
    cudaGetSymbolAddress((void**)&wob, g_wob);
    cudaGetSymbolAddress((void**)&wos, g_wos);
    cudaGetSymbolAddress((void**)&qsb, g_qsb);
    cudaGetSymbolAddress((void**)&qss, g_qss);
    cudaGetSymbolAddress((void**)&ksb, g_ksb);
    cudaGetSymbolAddress((void**)&kss, g_kss);
    cudaGetSymbolAddress((void**)&vtb, g_vtb);
    cudaGetSymbolAddress((void**)&vts, g_vts);

    cudaFuncSetAttribute(bgemm256<0>, cudaFuncAttributeMaxDynamicSharedMemorySize, GEMM_DYN);
    cudaFuncSetAttribute(bgemm256<1>, cudaFuncAttributeMaxDynamicSharedMemorySize, GEMM_DYN);
    cudaFuncSetAttribute(flash_tc,    cudaFuncAttributeMaxDynamicSharedMemorySize, FLASH_DYN);

    dim3 tr_grid(Dx / 32, Dx / 32);
    const int nH4 = (Mx * Dx) / 4;
    const size_t WHALF = (size_t)Dx * Dx / 2;

    // Prep: split hidden + all four weights (QKV into one concatenated buffer)
    split_kernel<<<(nH4 + 255) / 256, 256>>>(hidden, hb, hs, nH4);
    split_t_kernel<<<tr_grid, 256>>>(Wq, w3b,             w3s);
    split_t_kernel<<<tr_grid, 256>>>(Wk, w3b + WHALF,     w3s + WHALF);
    split_t_kernel<<<tr_grid, 256>>>(Wv, w3b + 2 * WHALF, w3s + 2 * WHALF);
    split_t_kernel<<<tr_grid, 256>>>(Wo, wob, wos);

    // Fused QKV projection: one launch, 768 CTAs.
    bgemm256<1><<<dim3(24, Mx / 128), 512, GEMM_DYN>>>(hb, hs, w3b, w3s, q, k, v);

    rope_split_kernel<<<(32 * Sx) / 4, 128>>>(q, k, qsb, qss, ksb, kss);
    vsplit_t_kernel<<<dim3(Sx / 32, HDx / 32, 32), 256>>>(v, vtb, vts);

    // Flash writes split ctx directly into hb/hs.
    flash_tc<<<dim3(16, 32), 256, FLASH_DYN>>>(qsb, qss, ksb, kss, vtb, vts, hb, hs);

    // Output projection reads hb/hs directly.
    bgemm256<0><<<dim3(8, Mx / 128), 512, GEMM_DYN>>>(hb, hs, wob, wos,
                                                      (float*)d_out, nullptr, nullptr);
}

// round 15
// speedup vs baseline: 4.5009x; 2.2376x over previous
#include <cuda_runtime.h>
#include <cuda_fp16.h>
#include <math.h>
#include <stdint.h>

// Problem constants
#define Bx 2
#define Sx 2048
#define Dx 2048
#define Hx 16
#define HDx 128
#define Mx (Bx*Sx)   // 4096

// Scratch (device globals; no allocation allowed)
__device__ float g_q[(size_t)Mx * Dx];
__device__ float g_k[(size_t)Mx * Dx];
__device__ float g_v[(size_t)Mx * Dx];
// fp16 operand buffers (packed half2 words along K)
__device__ uint32_t g_h16[(size_t)Mx * Dx / 2];     // hidden, later ctx
__device__ uint32_t g_wq16[(size_t)Dx * Dx / 2];    // weights, K-major [N][K/2]
__device__ uint32_t g_wk16[(size_t)Dx * Dx / 2];
__device__ uint32_t g_wv16[(size_t)Dx * Dx / 2];
__device__ uint32_t g_wo16[(size_t)Dx * Dx / 2];
// Flash operands: roped q,k fp16 pairs [bh][s][64 words]; V^T fp16 [bh][d][1024 words]
__device__ uint32_t g_q16[(size_t)32 * 2048 * 64];
__device__ uint32_t g_k16[(size_t)32 * 2048 * 64];
__device__ uint32_t g_vt16[(size_t)32 * 128 * 1024];

// ---------------------------------------------------------------------------
// Helpers
// ---------------------------------------------------------------------------
__device__ __forceinline__ void cpa16(void* smem, const void* gmem) {
    uint32_t s = (uint32_t)__cvta_generic_to_shared(smem);
    asm volatile("cp.async.cg.shared.global [%0], [%1], 16;\n" :: "r"(s), "l"(gmem));
}
__device__ __forceinline__ void cpa_commit() {
    asm volatile("cp.async.commit_group;\n");
}
__device__ __forceinline__ uint32_t pack_h2(float x, float y) {
    __half2 h = __floats2half2_rn(x, y);
    return *(uint32_t*)&h;
}
__device__ __forceinline__ void mma_f16(float c[4], const uint32_t a[4], const uint32_t b[2]) {
    asm volatile(
        "mma.sync.aligned.m16n8k16.row.col.f32.f16.f16.f32 "
        "{%0,%1,%2,%3},{%4,%5,%6,%7},{%8,%9},{%0,%1,%2,%3};\n"
        : "+f"(c[0]), "+f"(c[1]), "+f"(c[2]), "+f"(c[3])
        : "r"(a[0]), "r"(a[1]), "r"(a[2]), "r"(a[3]), "r"(b[0]), "r"(b[1]));
}

// ---------------------------------------------------------------------------
// fp16 convert (row-major): float4 -> 2 packed half2 words
// ---------------------------------------------------------------------------
__global__ __launch_bounds__(256)
void cvt_kernel(const float* __restrict__ X, uint32_t* __restrict__ H, int n4) {
    int i = blockIdx.x * 256 + threadIdx.x;
    if (i >= n4) return;
    float4 x = ((const float4*)X)[i];
    uint2 h;
    h.x = pack_h2(x.x, x.y);
    h.y = pack_h2(x.z, x.w);
    ((uint2*)H)[i] = h;
}

// ---------------------------------------------------------------------------
// fp16 convert + transpose weights: W[K,N] fp32 -> T[N, K/2] half2 words.
// ---------------------------------------------------------------------------
__global__ __launch_bounds__(256)
void cvt_t_kernel(const float* __restrict__ W, uint32_t* __restrict__ T) {
    __shared__ float t[32][33];
    int n0 = blockIdx.x * 32, k0 = blockIdx.y * 32;
    int tx = threadIdx.x & 31, ty = threadIdx.x >> 5;
#pragma unroll
    for (int i = 0; i < 4; ++i)
        t[ty + i * 8][tx] = W[(size_t)(k0 + ty + i * 8) * Dx + n0 + tx];
    __syncthreads();
    int kp = threadIdx.x & 15;
    int ny = threadIdx.x >> 4;
#pragma unroll
    for (int i = 0; i < 2; ++i) {
        int nl = ny + i * 16;
        size_t o = (size_t)(n0 + nl) * (Dx / 2) + (k0 / 2) + kp;
        T[o] = pack_h2(t[2 * kp][nl], t[2 * kp + 1][nl]);
    }
}

// ---------------------------------------------------------------------------
// FP16 single-term mma.sync GEMM, 512 thr, 128x256 tile, KT=64.
// A row-major [M,K]; B K-major [N,K]; packed half2 words. fp32 out.
// 16 warps (2m x 8n), 64x32 per warp. cp.async double buffering.
// Word-LD=36 -> conflict-free fragment LDS.
// OUT_MODE 0: row-major [M,2048].  OUT_MODE 1: [B,H,S,HD] (BN=256 = 2 heads).
// ---------------------------------------------------------------------------
#define T_LDW 36
#define AT_W (128 * T_LDW)            // 4608 words
#define BT_W (256 * T_LDW)            // 9216 words
#define STG_W (AT_W + BT_W)           // 13824 words per stage
#define GEMM_DYN (2 * STG_W * 4)      // 110592 bytes

template <int OUT_MODE>
__global__ __launch_bounds__(512)
void hgemm256(const uint32_t* __restrict__ A, const uint32_t* __restrict__ W,
              float* __restrict__ C) {
    extern __shared__ uint32_t sm[];
    const int tid  = threadIdx.x;
    const int lane = tid & 31;
    const int warp = tid >> 5;
    const int wm   = warp & 1;
    const int wn   = warp >> 1;
    const int KW = Dx / 2;
    const size_t aoff = (size_t)blockIdx.y * 128 * KW;
    const size_t boff = (size_t)blockIdx.x * 256 * KW;

    float acc[4][4][4];
#pragma unroll
    for (int i = 0; i < 4; ++i)
#pragma unroll
        for (int j = 0; j < 4; ++j)
#pragma unroll
            for (int t = 0; t < 4; ++t) acc[i][j][t] = 0.f;

    // Stage layout (words): A[AT_W] B[BT_W]
    auto loadTiles = [&](int kt, int stg) {       // kt in elements (mult of 64)
        uint32_t* sb = sm + stg * STG_W;
        const int kw = kt / 2;                    // 32 words per tile row
        // A: 128 rows x 8 chunks = 1024 / 512 thr
#pragma unroll
        for (int i = 0; i < 2; ++i) {
            int c = tid + 512 * i;
            int r = c >> 3, o = (c & 7) << 2;
            cpa16(sb + r * T_LDW + o, A + aoff + (size_t)r * KW + kw + o);
        }
        // B: 256 rows x 8 chunks = 2048 / 512 thr
#pragma unroll
        for (int i = 0; i < 4; ++i) {
            int c = tid + 512 * i;
            int r = c >> 3, o = (c & 7) << 2;
            cpa16(sb + AT_W + r * T_LDW + o, W + boff + (size_t)r * KW + kw + o);
        }
    };

    const int NT = Dx / 64;            // 32 chunks
    loadTiles(0, 0); cpa_commit();

    for (int it = 0; it < NT; ++it) {
        if (it + 1 < NT) {
            loadTiles((it + 1) * 64, (it + 1) & 1);
            cpa_commit();
            asm volatile("cp.async.wait_group 1;\n" ::: "memory");
        } else {
            asm volatile("cp.async.wait_group 0;\n" ::: "memory");
        }
        __syncthreads();

        const uint32_t* Ab = sm + (it & 1) * STG_W;
        const uint32_t* Bb = Ab + AT_W;

#pragma unroll
        for (int kk = 0; kk < 4; ++kk) {          // four k16 slices
            const int kw0 = kk * 8;
            uint32_t af[4][4];
#pragma unroll
            for (int mf = 0; mf < 4; ++mf) {
                int r0 = wm * 64 + mf * 16 + (lane >> 2);
                int base = r0 * T_LDW + kw0 + (lane & 3);
                af[mf][0] = Ab[base];
                af[mf][1] = Ab[base + 8 * T_LDW];
                af[mf][2] = Ab[base + 4];
                af[mf][3] = Ab[base + 8 * T_LDW + 4];
            }
            uint32_t bf[4][2];
#pragma unroll
            for (int nf = 0; nf < 4; ++nf) {
                int col = wn * 32 + nf * 8 + (lane >> 2);
                int base = col * T_LDW + kw0 + (lane & 3);
                bf[nf][0] = Bb[base];
                bf[nf][1] = Bb[base + 4];
            }
#pragma unroll
            for (int mf = 0; mf < 4; ++mf)
#pragma unroll
                for (int nf = 0; nf < 4; ++nf)
                    mma_f16(acc[mf][nf], af[mf], bf[nf]);
        }
        __syncthreads();
    }

    // Epilogue
#pragma unroll
    for (int mf = 0; mf < 4; ++mf) {
#pragma unroll
        for (int nf = 0; nf < 4; ++nf) {
            int r0 = blockIdx.y * 128 + wm * 64 + mf * 16 + (lane >> 2);
            int r1 = r0 + 8;
            int cb = wn * 32 + nf * 8 + 2 * (lane & 3);
            float2 v0 = make_float2(acc[mf][nf][0], acc[mf][nf][1]);
            float2 v1 = make_float2(acc[mf][nf][2], acc[mf][nf][3]);
            if (OUT_MODE == 0) {
                *(float2*)(C + (size_t)r0 * Dx + blockIdx.x * 256 + cb) = v0;
                *(float2*)(C + (size_t)r1 * Dx + blockIdx.x * 256 + cb) = v1;
            } else {
                int h  = blockIdx.x * 2 + (cb >> 7);
                int hd = cb & 127;
                int b0 = r0 >> 11, s0 = r0 & 2047;
                int b1 = r1 >> 11, s1 = r1 & 2047;
                *(float2*)(C + (((size_t)b0 * Hx + h) * Sx + s0) * HDx + hd) = v0;
                *(float2*)(C + (((size_t)b1 * Hx + h) * Sx + s1) * HDx + hd) = v1;
            }
        }
    }
}

// ---------------------------------------------------------------------------
// RoPE + fp16 convert: reads fp32 q,k [bh][s][128], writes half2 pairs
// [bh*2048+s][64 words].
// ---------------------------------------------------------------------------
__global__ __launch_bounds__(128)
void rope_h_kernel(const float* __restrict__ q, const float* __restrict__ k,
                   uint32_t* __restrict__ qh, uint32_t* __restrict__ kh) {
    int row = blockIdx.x * 4 + (threadIdx.x >> 5);
    int j   = threadIdx.x & 31;
    int s   = row & (Sx - 1);
    float pos = (float)s;
    const float L = logf(10000.0f);
    float a0 = pos * expf(-L * (4.0f * j)        / 128.0f);
    float a1 = pos * expf(-L * (4.0f * j + 2.0f) / 128.0f);
    float c0, sn0, c1, sn1;
    sincosf(a0, &sn0, &c0);
    sincosf(a1, &sn1, &c1);

    const float* qr = q + (size_t)row * HDx;
    const float* kr = k + (size_t)row * HDx;
    size_t ob = (size_t)row * 64;

    {
        float x0 = qr[2*j], x1 = qr[2*j+1], y0 = qr[2*j+64], y1 = qr[2*j+65];
        qh[ob + j]      = pack_h2(x0 * c0 - y0 * sn0, x1 * c1 - y1 * sn1);
        qh[ob + 32 + j] = pack_h2(y0 * c0 + x0 * sn0, y1 * c1 + x1 * sn1);
    }
    {
        float x0 = kr[2*j], x1 = kr[2*j+1], y0 = kr[2*j+64], y1 = kr[2*j+65];
        kh[ob + j]      = pack_h2(x0 * c0 - y0 * sn0, x1 * c1 - y1 * sn1);
        kh[ob + 32 + j] = pack_h2(y0 * c0 + x0 * sn0, y1 * c1 + x1 * sn1);
    }
}

// ---------------------------------------------------------------------------
// V transpose + fp16: v fp32 [bh][s][128] -> vt [bh][d][1024 half2 words]
// ---------------------------------------------------------------------------
__global__ __launch_bounds__(256)
void vcvt_t_kernel(const float* __restrict__ v, uint32_t* __restrict__ T) {
    __shared__ float t[32][33];
    int s0 = blockIdx.x * 32, d0 = blockIdx.y * 32, bh = blockIdx.z;
    int tx = threadIdx.x & 31, ty = threadIdx.x >> 5;
#pragma unroll
    for (int i = 0; i < 4; ++i) {
        int sl = ty + i * 8;
        t[sl][tx] = v[((size_t)bh * Sx + s0 + sl) * HDx + d0 + tx];
    }
    __syncthreads();
    int r  = threadIdx.x >> 3;
    int wq = threadIdx.x & 7;
    size_t o = ((size_t)bh * HDx + d0 + r) * (Sx / 2) + (s0 >> 1) + 2 * wq;
    T[o]     = pack_h2(t[4*wq][r],   t[4*wq+1][r]);
    T[o + 1] = pack_h2(t[4*wq+2][r], t[4*wq+3][r]);
}

// ---------------------------------------------------------------------------
// Tensor-core flash attention (fp16 single-term, fp32 softmax, causal).
// CTA = (qt: 128 rows, bh). 256 thr = 8 warps x m16. Bc=64.
// Writes ctx as fp16 half2 words into g_h16 (row [b*S+s], word h*64+d/2).
// ---------------------------------------------------------------------------
#define FQ_LD 68
#define FV_LD 36
#define FOQS (128 * FQ_LD)            // 8704
#define FK_W (64 * FQ_LD)             // 4352
#define FV_W (128 * FV_LD)            // 4608
#define FSTG_W (FK_W + FV_W)          // 8960
#define FLASH_DYN ((FOQS + 2 * FSTG_W) * 4)   // 106496 bytes

__global__ __launch_bounds__(256)
void flash_h(const uint32_t* __restrict__ Qh_, const uint32_t* __restrict__ Kh_,
             const uint32_t* __restrict__ Vh_, uint32_t* __restrict__ Oh_) {
    extern __shared__ uint32_t sw[];
    const int tid  = threadIdx.x;
    const int lane = tid & 31;
    const int warp = tid >> 5;
    const int qt   = 15 - blockIdx.x;     // heavy tiles first
    const int bh   = blockIdx.y;

    const size_t qbase = ((size_t)bh * Sx + qt * 128) * 64;
#pragma unroll
    for (int i = 0; i < 8; ++i) {
        int c = tid + 256 * i;            // 0..2047
        int r = c >> 4, w4 = (c & 15) * 4;
        cpa16(sw + r * FQ_LD + w4, Qh_ + qbase + r * 64 + w4);
    }

    auto loadKV = [&](int kt, int stg) {
        uint32_t* sb = sw + FOQS + stg * FSTG_W;
        const size_t kbase = ((size_t)bh * Sx + kt * 64) * 64;
#pragma unroll
        for (int i = 0; i < 4; ++i) {
            int c = tid + 256 * i;        // 0..1023
            int r = c >> 4, w4 = (c & 15) * 4;
            cpa16(sb + r * FQ_LD + w4, Kh_ + kbase + r * 64 + w4);
        }
        const size_t vbase = (size_t)bh * HDx * (Sx / 2) + kt * 32;
#pragma unroll
        for (int i = 0; i < 4; ++i) {
            int c = tid + 256 * i;        // 0..1023
            int d = c >> 3, w4 = (c & 7) * 4;
            cpa16(sb + FK_W + d * FV_LD + w4, Vh_ + vbase + (size_t)d * (Sx / 2) + w4);
        }
    };

    float o[16][4];
#pragma unroll
    for (int i = 0; i < 16; ++i)
#pragma unroll
        for (int t = 0; t < 4; ++t) o[i][t] = 0.f;
    float m0 = -INFINITY, m1 = -INFINITY, l0 = 0.f, l1 = 0.f;

    const float scale = 0.08838834764831845f;
    const int ktmax = 2 * qt + 1;
    loadKV(0, 0); cpa_commit();

    for (int kt = 0; kt <= ktmax; ++kt) {
        const int stg = kt & 1;
        if (kt < ktmax) {
            loadKV(kt + 1, stg ^ 1);
            cpa_commit();
            asm volatile("cp.async.wait_group 1;\n" ::: "memory");
        } else {
            asm volatile("cp.async.wait_group 0;\n" ::: "memory");
        }
        __syncthreads();

        const uint32_t* Kb = sw + FOQS + stg * FSTG_W;
        const uint32_t* Vb = Kb + FK_W;
        const uint32_t* Qb = sw;

        // S = Q K^T
        float s[8][4];
#pragma unroll
        for (int nf = 0; nf < 8; ++nf)
#pragma unroll
            for (int t = 0; t < 4; ++t) s[nf][t] = 0.f;

#pragma unroll
        for (int ksl = 0; ksl < 8; ++ksl) {
            int ab = (warp * 16 + (lane >> 2)) * FQ_LD + ksl * 8 + (lane & 3);
            uint32_t qf[4] = {Qb[ab], Qb[ab + 8 * FQ_LD], Qb[ab + 4], Qb[ab + 8 * FQ_LD + 4]};
#pragma unroll
            for (int nf = 0; nf < 8; ++nf) {
                int bb = (nf * 8 + (lane >> 2)) * FQ_LD + ksl * 8 + (lane & 3);
                uint32_t kf[2] = {Kb[bb], Kb[bb + 4]};
                mma_f16(s[nf], qf, kf);
            }
        }

        // scale + causal mask
        const int rg0 = qt * 128 + warp * 16 + (lane >> 2);
        const int rg1 = rg0 + 8;
        const bool needmask = (kt >= 2 * qt);
#pragma unroll
        for (int nf = 0; nf < 8; ++nf) {
            int cb = kt * 64 + nf * 8 + 2 * (lane & 3);
#pragma unroll
            for (int t = 0; t < 4; ++t) {
                s[nf][t] *= scale;
                if (needmask) {
                    int col = cb + (t & 1);
                    int row = (t < 2) ? rg0 : rg1;
                    if (col > row) s[nf][t] = -1e30f;
                }
            }
        }

        // online softmax
        float mx0 = -1e30f, mx1 = -1e30f;
#pragma unroll
        for (int nf = 0; nf < 8; ++nf) {
            mx0 = fmaxf(mx0, fmaxf(s[nf][0], s[nf][1]));
            mx1 = fmaxf(mx1, fmaxf(s[nf][2], s[nf][3]));
        }
        mx0 = fmaxf(mx0, __shfl_xor_sync(0xffffffffu, mx0, 1));
        mx0 = fmaxf(mx0, __shfl_xor_sync(0xffffffffu, mx0, 2));
        mx1 = fmaxf(mx1, __shfl_xor_sync(0xffffffffu, mx1, 1));
        mx1 = fmaxf(mx1, __shfl_xor_sync(0xffffffffu, mx1, 2));
        float mn0 = fmaxf(m0, mx0), mn1 = fmaxf(m1, mx1);
        float al0 = expf(m0 - mn0), al1 = expf(m1 - mn1);
        float ps0 = 0.f, ps1 = 0.f;
#pragma unroll
        for (int nf = 0; nf < 8; ++nf) {
            s[nf][0] = expf(s[nf][0] - mn0);
            s[nf][1] = expf(s[nf][1] - mn0);
            s[nf][2] = expf(s[nf][2] - mn1);
            s[nf][3] = expf(s[nf][3] - mn1);
            ps0 += s[nf][0] + s[nf][1];
            ps1 += s[nf][2] + s[nf][3];
        }
        ps0 += __shfl_xor_sync(0xffffffffu, ps0, 1);
        ps0 += __shfl_xor_sync(0xffffffffu, ps0, 2);
        ps1 += __shfl_xor_sync(0xffffffffu, ps1, 1);
        ps1 += __shfl_xor_sync(0xffffffffu, ps1, 2);
        l0 = l0 * al0 + ps0;
        l1 = l1 * al1 + ps1;
        m0 = mn0; m1 = mn1;
#pragma unroll
        for (int nf = 0; nf < 16; ++nf) {
            o[nf][0] *= al0; o[nf][1] *= al0;
            o[nf][2] *= al1; o[nf][3] *= al1;
        }

        // P fragments (fp16 pack)
        uint32_t pf[4][4];
#pragma unroll
        for (int j = 0; j < 4; ++j) {
            pf[j][0] = pack_h2(s[2*j][0],   s[2*j][1]);
            pf[j][1] = pack_h2(s[2*j][2],   s[2*j][3]);
            pf[j][2] = pack_h2(s[2*j+1][0], s[2*j+1][1]);
            pf[j][3] = pack_h2(s[2*j+1][2], s[2*j+1][3]);
        }

        // O += P V
#pragma unroll
        for (int j = 0; j < 4; ++j) {
#pragma unroll
            for (int nf = 0; nf < 16; ++nf) {
                int vb = (nf * 8 + (lane >> 2)) * FV_LD + j * 8 + (lane & 3);
                uint32_t vf[2] = {Vb[vb], Vb[vb + 4]};
                mma_f16(o[nf], pf[j], vf);
            }
        }
        __syncthreads();
    }

    // Epilogue: normalize and write ctx as fp16 pairs straight into g_h16.
    const int b = bh >> 4;
    const int h = bh & 15;
    const float inv0 = 1.0f / l0;
    const float inv1 = 1.0f / l1;
    const int r0g = qt * 128 + warp * 16 + (lane >> 2);
    const int r1g = r0g + 8;
    const size_t row0 = ((size_t)b * Sx + r0g) * 1024 + h * 64;
    const size_t row1 = ((size_t)b * Sx + r1g) * 1024 + h * 64;
#pragma unroll
    for (int nf = 0; nf < 16; ++nf) {
        int dw = (nf * 8 + 2 * (lane & 3)) >> 1;
        Oh_[row0 + dw] = pack_h2(o[nf][0] * inv0, o[nf][1] * inv0);
        Oh_[row1 + dw] = pack_h2(o[nf][2] * inv1, o[nf][3] * inv1);
    }
}

// ---------------------------------------------------------------------------
// Launch
// ---------------------------------------------------------------------------
extern "C" void kernel_launch(void* const* d_in, const int* in_sizes, int n_in,
                              void* d_out, int out_size) {
    const float* hidden = (const float*)d_in[0];
    const float* Wq = (const float*)d_in[3];
    const float* Wk = (const float*)d_in[4];
    const float* Wv = (const float*)d_in[5];
    const float* Wo = (const float*)d_in[6];

    float *q, *k, *v;
    uint32_t *h16, *wq16, *wk16, *wv16, *wo16, *q16, *k16, *vt16;
    cudaGetSymbolAddress((void**)&q,    g_q);
    cudaGetSymbolAddress((void**)&k,    g_k);
    cudaGetSymbolAddress((void**)&v,    g_v);
    cudaGetSymbolAddress((void**)&h16,  g_h16);
    cudaGetSymbolAddress((void**)&wq16, g_wq16);
    cudaGetSymbolAddress((void**)&wk16, g_wk16);
    cudaGetSymbolAddress((void**)&wv16, g_wv16);
    cudaGetSymbolAddress((void**)&wo16, g_wo16);
    cudaGetSymbolAddress((void**)&q16,  g_q16);
    cudaGetSymbolAddress((void**)&k16,  g_k16);
    cudaGetSymbolAddress((void**)&vt16, g_vt16);

    cudaFuncSetAttribute(hgemm256<0>, cudaFuncAttributeMaxDynamicSharedMemorySize, GEMM_DYN);
    cudaFuncSetAttribute(hgemm256<1>, cudaFuncAttributeMaxDynamicSharedMemorySize, GEMM_DYN);
    cudaFuncSetAttribute(flash_h,     cudaFuncAttributeMaxDynamicSharedMemorySize, FLASH_DYN);

    dim3 gemm_grid(Dx / 256, Mx / 128);   // (8, 32)
    dim3 tr_grid(Dx / 32, Dx / 32);
    const int nH4 = (Mx * Dx) / 4;

    // Prep: fp16 convert hidden + all four weights
    cvt_kernel<<<(nH4 + 255) / 256, 256>>>(hidden, h16, nH4);
    cvt_t_kernel<<<tr_grid, 256>>>(Wq, wq16);
    cvt_t_kernel<<<tr_grid, 256>>>(Wk, wk16);
    cvt_t_kernel<<<tr_grid, 256>>>(Wv, wv16);
    cvt_t_kernel<<<tr_grid, 256>>>(Wo, wo16);

    // QKV projections -> [B,H,S,HD] fp32
    hgemm256<1><<<gemm_grid, 512, GEMM_DYN>>>(h16, wq16, q);
    hgemm256<1><<<gemm_grid, 512, GEMM_DYN>>>(h16, wk16, k);
    hgemm256<1><<<gemm_grid, 512, GEMM_DYN>>>(h16, wv16, v);

    // RoPE + fp16 convert q,k ; V transpose + fp16
    rope_h_kernel<<<(32 * Sx) / 4, 128>>>(q, k, q16, k16);
    vcvt_t_kernel<<<dim3(Sx / 32, HDx / 32, 32), 256>>>(v, vt16);

    // Flash attention (fp16 operands, fp32 softmax) -> ctx fp16 into h16
    flash_h<<<dim3(16, 32), 256, FLASH_DYN>>>(q16, k16, vt16, h16);

    // Output projection reads h16 directly.
    hgemm256<0><<<gemm_grid, 512, GEMM_DYN>>>(h16, wo16, (float*)d_out);
}

// round 16
// speedup vs baseline: 4.6570x; 1.0347x over previous
#include <cuda_runtime.h>
#include <cuda_fp16.h>
#include <math.h>
#include <stdint.h>

// Problem constants
#define Bx 2
#define Sx 2048
#define Dx 2048
#define Hx 16
#define HDx 128
#define Mx (Bx*Sx)   // 4096

// Scratch (device globals; no allocation allowed)
__device__ float g_q[(size_t)Mx * Dx];
__device__ float g_k[(size_t)Mx * Dx];
__device__ float g_v[(size_t)Mx * Dx];
// fp16 operand buffers (packed half2 words along K)
__device__ uint32_t g_h16[(size_t)Mx * Dx / 2];     // hidden, later ctx
__device__ uint32_t g_wq16[(size_t)Dx * Dx / 2];    // weights, K-major [N][K/2]
__device__ uint32_t g_wk16[(size_t)Dx * Dx / 2];
__device__ uint32_t g_wv16[(size_t)Dx * Dx / 2];
__device__ uint32_t g_wo16[(size_t)Dx * Dx / 2];
// Flash operands: roped q,k fp16 pairs [bh][s][64 words]; V^T fp16 [bh][d][1024 words]
__device__ uint32_t g_q16[(size_t)32 * 2048 * 64];
__device__ uint32_t g_k16[(size_t)32 * 2048 * 64];
__device__ uint32_t g_vt16[(size_t)32 * 128 * 1024];

// ---------------------------------------------------------------------------
// Helpers
// ---------------------------------------------------------------------------
__device__ __forceinline__ void cpa16(void* smem, const void* gmem) {
    uint32_t s = (uint32_t)__cvta_generic_to_shared(smem);
    asm volatile("cp.async.cg.shared.global [%0], [%1], 16;\n" :: "r"(s), "l"(gmem));
}
__device__ __forceinline__ void cpa_commit() {
    asm volatile("cp.async.commit_group;\n");
}
__device__ __forceinline__ uint32_t pack_h2(float x, float y) {
    __half2 h = __floats2half2_rn(x, y);
    return *(uint32_t*)&h;
}
__device__ __forceinline__ void mma_f16(float c[4], const uint32_t a[4], const uint32_t b[2]) {
    asm volatile(
        "mma.sync.aligned.m16n8k16.row.col.f32.f16.f16.f32 "
        "{%0,%1,%2,%3},{%4,%5,%6,%7},{%8,%9},{%0,%1,%2,%3};\n"
        : "+f"(c[0]), "+f"(c[1]), "+f"(c[2]), "+f"(c[3])
        : "r"(a[0]), "r"(a[1]), "r"(a[2]), "r"(a[3]), "r"(b[0]), "r"(b[1]));
}

// ---------------------------------------------------------------------------
// fp16 convert (row-major): float4 -> 2 packed half2 words
// ---------------------------------------------------------------------------
__global__ __launch_bounds__(256)
void cvt_kernel(const float* __restrict__ X, uint32_t* __restrict__ H, int n4) {
    int i = blockIdx.x * 256 + threadIdx.x;
    if (i >= n4) return;
    float4 x = ((const float4*)X)[i];
    uint2 h;
    h.x = pack_h2(x.x, x.y);
    h.y = pack_h2(x.z, x.w);
    ((uint2*)H)[i] = h;
}

// ---------------------------------------------------------------------------
// fp16 convert + transpose ALL FOUR weights in one launch (blockIdx.z picks).
// W[K,N] fp32 -> T[N, K/2] half2 words.
// ---------------------------------------------------------------------------
__global__ __launch_bounds__(256)
void cvt_t4_kernel(const float* __restrict__ W0, const float* __restrict__ W1,
                   const float* __restrict__ W2, const float* __restrict__ W3,
                   uint32_t* __restrict__ T0, uint32_t* __restrict__ T1,
                   uint32_t* __restrict__ T2, uint32_t* __restrict__ T3) {
    const int z = blockIdx.z;
    const float* W = (z == 0) ? W0 : (z == 1) ? W1 : (z == 2) ? W2 : W3;
    uint32_t*    T = (z == 0) ? T0 : (z == 1) ? T1 : (z == 2) ? T2 : T3;

    __shared__ float t[32][33];
    int n0 = blockIdx.x * 32, k0 = blockIdx.y * 32;
    int tx = threadIdx.x & 31, ty = threadIdx.x >> 5;
#pragma unroll
    for (int i = 0; i < 4; ++i)
        t[ty + i * 8][tx] = W[(size_t)(k0 + ty + i * 8) * Dx + n0 + tx];
    __syncthreads();
    int kp = threadIdx.x & 15;
    int ny = threadIdx.x >> 4;
#pragma unroll
    for (int i = 0; i < 2; ++i) {
        int nl = ny + i * 16;
        size_t o = (size_t)(n0 + nl) * (Dx / 2) + (k0 / 2) + kp;
        T[o] = pack_h2(t[2 * kp][nl], t[2 * kp + 1][nl]);
    }
}

// ---------------------------------------------------------------------------
// FP16 single-term mma.sync GEMM, 512 thr, 128x256 tile, KT=128.
// A row-major [M,K]; B K-major [N,K]; packed half2 words. fp32 out.
// 16 warps (2m x 8n), 64x32 per warp. cp.async double buffering.
// Word-LD=68 (64+4 pad) -> conflict-free fragment LDS (68 mod 32 = 4).
// OUT_MODE 0: row-major [M,2048].  OUT_MODE 1: [B,H,S,HD] (BN=256 = 2 heads).
// ---------------------------------------------------------------------------
#define T_LDW 68
#define AT_W (128 * T_LDW)            // 8704 words
#define BT_W (256 * T_LDW)            // 17408 words
#define STG_W (AT_W + BT_W)           // 26112 words per stage
#define GEMM_DYN (2 * STG_W * 4)      // 208896 bytes

template <int OUT_MODE>
__global__ __launch_bounds__(512)
void hgemm256(const uint32_t* __restrict__ A, const uint32_t* __restrict__ W,
              float* __restrict__ C) {
    extern __shared__ uint32_t sm[];
    const int tid  = threadIdx.x;
    const int lane = tid & 31;
    const int warp = tid >> 5;
    const int wm   = warp & 1;
    const int wn   = warp >> 1;
    const int KW = Dx / 2;
    const size_t aoff = (size_t)blockIdx.y * 128 * KW;
    const size_t boff = (size_t)blockIdx.x * 256 * KW;

    float acc[4][4][4];
#pragma unroll
    for (int i = 0; i < 4; ++i)
#pragma unroll
        for (int j = 0; j < 4; ++j)
#pragma unroll
            for (int t = 0; t < 4; ++t) acc[i][j][t] = 0.f;

    // Stage layout (words): A[AT_W] B[BT_W]. KT=128 -> 64 words per row.
    auto loadTiles = [&](int kt, int stg) {       // kt in elements (mult of 128)
        uint32_t* sb = sm + stg * STG_W;
        const int kw = kt / 2;
        // A: 128 rows x 16 chunks = 2048 / 512 thr
#pragma unroll
        for (int i = 0; i < 4; ++i) {
            int c = tid + 512 * i;
            int r = c >> 4, o = (c & 15) << 2;
            cpa16(sb + r * T_LDW + o, A + aoff + (size_t)r * KW + kw + o);
        }
        // B: 256 rows x 16 chunks = 4096 / 512 thr
#pragma unroll
        for (int i = 0; i < 8; ++i) {
            int c = tid + 512 * i;
            int r = c >> 4, o = (c & 15) << 2;
            cpa16(sb + AT_W + r * T_LDW + o, W + boff + (size_t)r * KW + kw + o);
        }
    };

    const int NT = Dx / 128;           // 16 chunks
    loadTiles(0, 0); cpa_commit();

    for (int it = 0; it < NT; ++it) {
        if (it + 1 < NT) {
            loadTiles((it + 1) * 128, (it + 1) & 1);
            cpa_commit();
            asm volatile("cp.async.wait_group 1;\n" ::: "memory");
        } else {
            asm volatile("cp.async.wait_group 0;\n" ::: "memory");
        }
        __syncthreads();

        const uint32_t* Ab = sm + (it & 1) * STG_W;
        const uint32_t* Bb = Ab + AT_W;

#pragma unroll
        for (int kk = 0; kk < 8; ++kk) {          // eight k16 slices
            const int kw0 = kk * 8;
            uint32_t af[4][4];
#pragma unroll
            for (int mf = 0; mf < 4; ++mf) {
                int r0 = wm * 64 + mf * 16 + (lane >> 2);
                int base = r0 * T_LDW + kw0 + (lane & 3);
                af[mf][0] = Ab[base];
                af[mf][1] = Ab[base + 8 * T_LDW];
                af[mf][2] = Ab[base + 4];
                af[mf][3] = Ab[base + 8 * T_LDW + 4];
            }
            uint32_t bf[4][2];
#pragma unroll
            for (int nf = 0; nf < 4; ++nf) {
                int col = wn * 32 + nf * 8 + (lane >> 2);
                int base = col * T_LDW + kw0 + (lane & 3);
                bf[nf][0] = Bb[base];
                bf[nf][1] = Bb[base + 4];
            }
#pragma unroll
            for (int mf = 0; mf < 4; ++mf)
#pragma unroll
                for (int nf = 0; nf < 4; ++nf)
                    mma_f16(acc[mf][nf], af[mf], bf[nf]);
        }
        __syncthreads();
    }

    // Epilogue
#pragma unroll
    for (int mf = 0; mf < 4; ++mf) {
#pragma unroll
        for (int nf = 0; nf < 4; ++nf) {
            int r0 = blockIdx.y * 128 + wm * 64 + mf * 16 + (lane >> 2);
            int r1 = r0 + 8;
            int cb = wn * 32 + nf * 8 + 2 * (lane & 3);
            float2 v0 = make_float2(acc[mf][nf][0], acc[mf][nf][1]);
            float2 v1 = make_float2(acc[mf][nf][2], acc[mf][nf][3]);
            if (OUT_MODE == 0) {
                *(float2*)(C + (size_t)r0 * Dx + blockIdx.x * 256 + cb) = v0;
                *(float2*)(C + (size_t)r1 * Dx + blockIdx.x * 256 + cb) = v1;
            } else {
                int h  = blockIdx.x * 2 + (cb >> 7);
                int hd = cb & 127;
                int b0 = r0 >> 11, s0 = r0 & 2047;
                int b1 = r1 >> 11, s1 = r1 & 2047;
                *(float2*)(C + (((size_t)b0 * Hx + h) * Sx + s0) * HDx + hd) = v0;
                *(float2*)(C + (((size_t)b1 * Hx + h) * Sx + s1) * HDx + hd) = v1;
            }
        }
    }
}

// ---------------------------------------------------------------------------
// RoPE + fp16 convert: reads fp32 q,k [bh][s][128], writes half2 pairs
// [bh*2048+s][64 words].
// ---------------------------------------------------------------------------
__global__ __launch_bounds__(128)
void rope_h_kernel(const float* __restrict__ q, const float* __restrict__ k,
                   uint32_t* __restrict__ qh, uint32_t* __restrict__ kh) {
    int row = blockIdx.x * 4 + (threadIdx.x >> 5);
    int j   = threadIdx.x & 31;
    int s   = row & (Sx - 1);
    float pos = (float)s;
    const float L = logf(10000.0f);
    float a0 = pos * expf(-L * (4.0f * j)        / 128.0f);
    float a1 = pos * expf(-L * (4.0f * j + 2.0f) / 128.0f);
    float c0, sn0, c1, sn1;
    sincosf(a0, &sn0, &c0);
    sincosf(a1, &sn1, &c1);

    const float* qr = q + (size_t)row * HDx;
    const float* kr = k + (size_t)row * HDx;
    size_t ob = (size_t)row * 64;

    {
        float x0 = qr[2*j], x1 = qr[2*j+1], y0 = qr[2*j+64], y1 = qr[2*j+65];
        qh[ob + j]      = pack_h2(x0 * c0 - y0 * sn0, x1 * c1 - y1 * sn1);
        qh[ob + 32 + j] = pack_h2(y0 * c0 + x0 * sn0, y1 * c1 + x1 * sn1);
    }
    {
        float x0 = kr[2*j], x1 = kr[2*j+1], y0 = kr[2*j+64], y1 = kr[2*j+65];
        kh[ob + j]      = pack_h2(x0 * c0 - y0 * sn0, x1 * c1 - y1 * sn1);
        kh[ob + 32 + j] = pack_h2(y0 * c0 + x0 * sn0, y1 * c1 + x1 * sn1);
    }
}

// ---------------------------------------------------------------------------
// V transpose + fp16: v fp32 [bh][s][128] -> vt [bh][d][1024 half2 words]
// ---------------------------------------------------------------------------
__global__ __launch_bounds__(256)
void vcvt_t_kernel(const float* __restrict__ v, uint32_t* __restrict__ T) {
    __shared__ float t[32][33];
    int s0 = blockIdx.x * 32, d0 = blockIdx.y * 32, bh = blockIdx.z;
    int tx = threadIdx.x & 31, ty = threadIdx.x >> 5;
#pragma unroll
    for (int i = 0; i < 4; ++i) {
        int sl = ty + i * 8;
        t[sl][tx] = v[((size_t)bh * Sx + s0 + sl) * HDx + d0 + tx];
    }
    __syncthreads();
    int r  = threadIdx.x >> 3;
    int wq = threadIdx.x & 7;
    size_t o = ((size_t)bh * HDx + d0 + r) * (Sx / 2) + (s0 >> 1) + 2 * wq;
    T[o]     = pack_h2(t[4*wq][r],   t[4*wq+1][r]);
    T[o + 1] = pack_h2(t[4*wq+2][r], t[4*wq+3][r]);
}

// ---------------------------------------------------------------------------
// Tensor-core flash attention (fp16 single-term, fp32 softmax, causal).
// CTA = (qt: 128 rows, bh). 256 thr = 8 warps x m16. Bc=64.
// Writes ctx as fp16 half2 words into g_h16 (row [b*S+s], word h*64+d/2).
// ---------------------------------------------------------------------------
#define FQ_LD 68
#define FV_LD 36
#define FOQS (128 * FQ_LD)            // 8704
#define FK_W (64 * FQ_LD)             // 4352
#define FV_W (128 * FV_LD)            // 4608
#define FSTG_W (FK_W + FV_W)          // 8960
#define FLASH_DYN ((FOQS + 2 * FSTG_W) * 4)   // 106496 bytes

__global__ __launch_bounds__(256)
void flash_h(const uint32_t* __restrict__ Qh_, const uint32_t* __restrict__ Kh_,
             const uint32_t* __restrict__ Vh_, uint32_t* __restrict__ Oh_) {
    extern __shared__ uint32_t sw[];
    const int tid  = threadIdx.x;
    const int lane = tid & 31;
    const int warp = tid >> 5;
    const int qt   = 15 - blockIdx.x;     // heavy tiles first
    const int bh   = blockIdx.y;

    const size_t qbase = ((size_t)bh * Sx + qt * 128) * 64;
#pragma unroll
    for (int i = 0; i < 8; ++i) {
        int c = tid + 256 * i;            // 0..2047
        int r = c >> 4, w4 = (c & 15) * 4;
        cpa16(sw + r * FQ_LD + w4, Qh_ + qbase + r * 64 + w4);
    }

    auto loadKV = [&](int kt, int stg) {
        uint32_t* sb = sw + FOQS + stg * FSTG_W;
        const size_t kbase = ((size_t)bh * Sx + kt * 64) * 64;
#pragma unroll
        for (int i = 0; i < 4; ++i) {
            int c = tid + 256 * i;        // 0..1023
            int r = c >> 4, w4 = (c & 15) * 4;
            cpa16(sb + r * FQ_LD + w4, Kh_ + kbase + r * 64 + w4);
        }
        const size_t vbase = (size_t)bh * HDx * (Sx / 2) + kt * 32;
#pragma unroll
        for (int i = 0; i < 4; ++i) {
            int c = tid + 256 * i;        // 0..1023
            int d = c >> 3, w4 = (c & 7) * 4;
            cpa16(sb + FK_W + d * FV_LD + w4, Vh_ + vbase + (size_t)d * (Sx / 2) + w4);
        }
    };

    float o[16][4];
#pragma unroll
    for (int i = 0; i < 16; ++i)
#pragma unroll
        for (int t = 0; t < 4; ++t) o[i][t] = 0.f;
    float m0 = -INFINITY, m1 = -INFINITY, l0 = 0.f, l1 = 0.f;

    const float scale = 0.08838834764831845f;
    const int ktmax = 2 * qt + 1;
    loadKV(0, 0); cpa_commit();

    for (int kt = 0; kt <= ktmax; ++kt) {
        const int stg = kt & 1;
        if (kt < ktmax) {
            loadKV(kt + 1, stg ^ 1);
            cpa_commit();
            asm volatile("cp.async.wait_group 1;\n" ::: "memory");
        } else {
            asm volatile("cp.async.wait_group 0;\n" ::: "memory");
        }
        __syncthreads();

        const uint32_t* Kb = sw + FOQS + stg * FSTG_W;
        const uint32_t* Vb = Kb + FK_W;
        const uint32_t* Qb = sw;

        // S = Q K^T
        float s[8][4];
#pragma unroll
        for (int nf = 0; nf < 8; ++nf)
#pragma unroll
            for (int t = 0; t < 4; ++t) s[nf][t] = 0.f;

#pragma unroll
        for (int ksl = 0; ksl < 8; ++ksl) {
            int ab = (warp * 16 + (lane >> 2)) * FQ_LD + ksl * 8 + (lane & 3);
            uint32_t qf[4] = {Qb[ab], Qb[ab + 8 * FQ_LD], Qb[ab + 4], Qb[ab + 8 * FQ_LD + 4]};
#pragma unroll
            for (int nf = 0; nf < 8; ++nf) {
                int bb = (nf * 8 + (lane >> 2)) * FQ_LD + ksl * 8 + (lane & 3);
                uint32_t kf[2] = {Kb[bb], Kb[bb + 4]};
                mma_f16(s[nf], qf, kf);
            }
        }

        // scale + causal mask
        const int rg0 = qt * 128 + warp * 16 + (lane >> 2);
        const int rg1 = rg0 + 8;
        const bool needmask = (kt >= 2 * qt);
#pragma unroll
        for (int nf = 0; nf < 8; ++nf) {
            int cb = kt * 64 + nf * 8 + 2 * (lane & 3);
#pragma unroll
            for (int t = 0; t < 4; ++t) {
                s[nf][t] *= scale;
                if (needmask) {
                    int col = cb + (t & 1);
                    int row = (t < 2) ? rg0 : rg1;
                    if (col > row) s[nf][t] = -1e30f;
                }
            }
        }

        // online softmax
        float mx0 = -1e30f, mx1 = -1e30f;
#pragma unroll
        for (int nf = 0; nf < 8; ++nf) {
            mx0 = fmaxf(mx0, fmaxf(s[nf][0], s[nf][1]));
            mx1 = fmaxf(mx1, fmaxf(s[nf][2], s[nf][3]));
        }
        mx0 = fmaxf(mx0, __shfl_xor_sync(0xffffffffu, mx0, 1));
        mx0 = fmaxf(mx0, __shfl_xor_sync(0xffffffffu, mx0, 2));
        mx1 = fmaxf(mx1, __shfl_xor_sync(0xffffffffu, mx1, 1));
        mx1 = fmaxf(mx1, __shfl_xor_sync(0xffffffffu, mx1, 2));
        float mn0 = fmaxf(m0, mx0), mn1 = fmaxf(m1, mx1);
        float al0 = expf(m0 - mn0), al1 = expf(m1 - mn1);
        float ps0 = 0.f, ps1 = 0.f;
#pragma unroll
        for (int nf = 0; nf < 8; ++nf) {
            s[nf][0] = expf(s[nf][0] - mn0);
            s[nf][1] = expf(s[nf][1] - mn0);
            s[nf][2] = expf(s[nf][2] - mn1);
            s[nf][3] = expf(s[nf][3] - mn1);
            ps0 += s[nf][0] + s[nf][1];
            ps1 += s[nf][2] + s[nf][3];
        }
        ps0 += __shfl_xor_sync(0xffffffffu, ps0, 1);
        ps0 += __shfl_xor_sync(0xffffffffu, ps0, 2);
        ps1 += __shfl_xor_sync(0xffffffffu, ps1, 1);
        ps1 += __shfl_xor_sync(0xffffffffu, ps1, 2);
        l0 = l0 * al0 + ps0;
        l1 = l1 * al1 + ps1;
        m0 = mn0; m1 = mn1;
#pragma unroll
        for (int nf = 0; nf < 16; ++nf) {
            o[nf][0] *= al0; o[nf][1] *= al0;
            o[nf][2] *= al1; o[nf][3] *= al1;
        }

        // P fragments (fp16 pack)
        uint32_t pf[4][4];
#pragma unroll
        for (int j = 0; j < 4; ++j) {
            pf[j][0] = pack_h2(s[2*j][0],   s[2*j][1]);
            pf[j][1] = pack_h2(s[2*j][2],   s[2*j][3]);
            pf[j][2] = pack_h2(s[2*j+1][0], s[2*j+1][1]);
            pf[j][3] = pack_h2(s[2*j+1][2], s[2*j+1][3]);
        }

        // O += P V
#pragma unroll
        for (int j = 0; j < 4; ++j) {
#pragma unroll
            for (int nf = 0; nf < 16; ++nf) {
                int vb = (nf * 8 + (lane >> 2)) * FV_LD + j * 8 + (lane & 3);
                uint32_t vf[2] = {Vb[vb], Vb[vb + 4]};
                mma_f16(o[nf], pf[j], vf);
            }
        }
        __syncthreads();
    }

    // Epilogue: normalize and write ctx as fp16 pairs straight into g_h16.
    const int b = bh >> 4;
    const int h = bh & 15;
    const float inv0 = 1.0f / l0;
    const float inv1 = 1.0f / l1;
    const int r0g = qt * 128 + warp * 16 + (lane >> 2);
    const int r1g = r0g + 8;
    const size_t row0 = ((size_t)b * Sx + r0g) * 1024 + h * 64;
    const size_t row1 = ((size_t)b * Sx + r1g) * 1024 + h * 64;
#pragma unroll
    for (int nf = 0; nf < 16; ++nf) {
        int dw = (nf * 8 + 2 * (lane & 3)) >> 1;
        Oh_[row0 + dw] = pack_h2(o[nf][0] * inv0, o[nf][1] * inv0);
        Oh_[row1 + dw] = pack_h2(o[nf][2] * inv1, o[nf][3] * inv1);
    }
}

// ---------------------------------------------------------------------------
// Launch
// ---------------------------------------------------------------------------
extern "C" void kernel_launch(void* const* d_in, const int* in_sizes, int n_in,
                              void* d_out, int out_size) {
    const float* hidden = (const float*)d_in[0];
    const float* Wq = (const float*)d_in[3];
    const float* Wk = (const float*)d_in[4];
    const float* Wv = (const float*)d_in[5];
    const float* Wo = (const float*)d_in[6];

    float *q, *k, *v;
    uint32_t *h16, *wq16, *wk16, *wv16, *wo16, *q16, *k16, *vt16;
    cudaGetSymbolAddress((void**)&q,    g_q);
    cudaGetSymbolAddress((void**)&k,    g_k);
    cudaGetSymbolAddress((void**)&v,    g_v);
    cudaGetSymbolAddress((void**)&h16,  g_h16);
    cudaGetSymbolAddress((void**)&wq16, g_wq16);
    cudaGetSymbolAddress((void**)&wk16, g_wk16);
    cudaGetSymbolAddress((void**)&wv16, g_wv16);
    cudaGetSymbolAddress((void**)&wo16, g_wo16);
    cudaGetSymbolAddress((void**)&q16,  g_q16);
    cudaGetSymbolAddress((void**)&k16,  g_k16);
    cudaGetSymbolAddress((void**)&vt16, g_vt16);

    cudaFuncSetAttribute(hgemm256<0>, cudaFuncAttributeMaxDynamicSharedMemorySize, GEMM_DYN);
    cudaFuncSetAttribute(hgemm256<1>, cudaFuncAttributeMaxDynamicSharedMemorySize, GEMM_DYN);
    cudaFuncSetAttribute(flash_h,     cudaFuncAttributeMaxDynamicSharedMemorySize, FLASH_DYN);

    dim3 gemm_grid(Dx / 256, Mx / 128);   // (8, 32)
    const int nH4 = (Mx * Dx) / 4;

    // Prep: fp16 convert hidden + all four weights (one fused launch)
    cvt_kernel<<<(nH4 + 255) / 256, 256>>>(hidden, h16, nH4);
    cvt_t4_kernel<<<dim3(Dx / 32, Dx / 32, 4), 256>>>(Wq, Wk, Wv, Wo,
                                                      wq16, wk16, wv16, wo16);

    // QKV projections -> [B,H,S,HD] fp32
    hgemm256<1><<<gemm_grid, 512, GEMM_DYN>>>(h16, wq16, q);
    hgemm256<1><<<gemm_grid, 512, GEMM_DYN>>>(h16, wk16, k);
    hgemm256<1><<<gemm_grid, 512, GEMM_DYN>>>(h16, wv16, v);

    // RoPE + fp16 convert q,k ; V transpose + fp16
    rope_h_kernel<<<(32 * Sx) / 4, 128>>>(q, k, q16, k16);
    vcvt_t_kernel<<<dim3(Sx / 32, HDx / 32, 32), 256>>>(v, vt16);

    // Flash attention (fp16 operands, fp32 softmax) -> ctx fp16 into h16
    flash_h<<<dim3(16, 32), 256, FLASH_DYN>>>(q16, k16, vt16, h16);

    // Output projection reads h16 directly.
    hgemm256<0><<<gemm_grid, 512, GEMM_DYN>>>(h16, wo16, (float*)d_out);
}

// round 17
// speedup vs baseline: 4.8734x; 1.0465x over previous
#include <cuda_runtime.h>
#include <cuda_fp16.h>
#include <math.h>
#include <stdint.h>

// Problem constants
#define Bx 2
#define Sx 2048
#define Dx 2048
#define Hx 16
#define HDx 128
#define Mx (Bx*Sx)   // 4096

// Scratch (device globals; no allocation allowed)
__device__ float g_q[(size_t)Mx * Dx];
__device__ float g_k[(size_t)Mx * Dx];
__device__ float g_v[(size_t)Mx * Dx];
// fp16 operand buffers (packed half2 words along K)
__device__ uint32_t g_h16[(size_t)Mx * Dx / 2];     // hidden, later ctx
__device__ uint32_t g_wq16[(size_t)Dx * Dx / 2];    // weights, K-major [N][K/2]
__device__ uint32_t g_wk16[(size_t)Dx * Dx / 2];
__device__ uint32_t g_wv16[(size_t)Dx * Dx / 2];
__device__ uint32_t g_wo16[(size_t)Dx * Dx / 2];
// Flash operands: roped q,k fp16 pairs [bh][s][64 words]; V^T fp16 [bh][d][1024 words]
__device__ uint32_t g_q16[(size_t)32 * 2048 * 64];
__device__ uint32_t g_k16[(size_t)32 * 2048 * 64];
__device__ uint32_t g_vt16[(size_t)32 * 128 * 1024];

// ---------------------------------------------------------------------------
// Helpers
// ---------------------------------------------------------------------------
__device__ __forceinline__ void cpa16(void* smem, const void* gmem) {
    uint32_t s = (uint32_t)__cvta_generic_to_shared(smem);
    asm volatile("cp.async.cg.shared.global [%0], [%1], 16;\n" :: "r"(s), "l"(gmem));
}
__device__ __forceinline__ void cpa_commit() {
    asm volatile("cp.async.commit_group;\n");
}
__device__ __forceinline__ uint32_t pack_h2(float x, float y) {
    __half2 h = __floats2half2_rn(x, y);
    return *(uint32_t*)&h;
}
__device__ __forceinline__ void mma_f16(float c[4], const uint32_t a[4], const uint32_t b[2]) {
    asm volatile(
        "mma.sync.aligned.m16n8k16.row.col.f32.f16.f16.f32 "
        "{%0,%1,%2,%3},{%4,%5,%6,%7},{%8,%9},{%0,%1,%2,%3};\n"
        : "+f"(c[0]), "+f"(c[1]), "+f"(c[2]), "+f"(c[3])
        : "r"(a[0]), "r"(a[1]), "r"(a[2]), "r"(a[3]), "r"(b[0]), "r"(b[1]));
}
__device__ __forceinline__ void ldsm4(uint32_t r[4], uint32_t saddr) {
    asm volatile(
        "ldmatrix.sync.aligned.m8n8.x4.shared.b16 {%0,%1,%2,%3}, [%4];"
        : "=r"(r[0]), "=r"(r[1]), "=r"(r[2]), "=r"(r[3]) : "r"(saddr));
}

// ---------------------------------------------------------------------------
// fp16 convert (row-major): float4 -> 2 packed half2 words
// ---------------------------------------------------------------------------
__global__ __launch_bounds__(256)
void cvt_kernel(const float* __restrict__ X, uint32_t* __restrict__ H, int n4) {
    int i = blockIdx.x * 256 + threadIdx.x;
    if (i >= n4) return;
    float4 x = ((const float4*)X)[i];
    uint2 h;
    h.x = pack_h2(x.x, x.y);
    h.y = pack_h2(x.z, x.w);
    ((uint2*)H)[i] = h;
}

// ---------------------------------------------------------------------------
// fp16 convert + transpose ALL FOUR weights in one launch (blockIdx.z picks).
// ---------------------------------------------------------------------------
__global__ __launch_bounds__(256)
void cvt_t4_kernel(const float* __restrict__ W0, const float* __restrict__ W1,
                   const float* __restrict__ W2, const float* __restrict__ W3,
                   uint32_t* __restrict__ T0, uint32_t* __restrict__ T1,
                   uint32_t* __restrict__ T2, uint32_t* __restrict__ T3) {
    const int z = blockIdx.z;
    const float* W = (z == 0) ? W0 : (z == 1) ? W1 : (z == 2) ? W2 : W3;
    uint32_t*    T = (z == 0) ? T0 : (z == 1) ? T1 : (z == 2) ? T2 : T3;

    __shared__ float t[32][33];
    int n0 = blockIdx.x * 32, k0 = blockIdx.y * 32;
    int tx = threadIdx.x & 31, ty = threadIdx.x >> 5;
#pragma unroll
    for (int i = 0; i < 4; ++i)
        t[ty + i * 8][tx] = W[(size_t)(k0 + ty + i * 8) * Dx + n0 + tx];
    __syncthreads();
    int kp = threadIdx.x & 15;
    int ny = threadIdx.x >> 4;
#pragma unroll
    for (int i = 0; i < 2; ++i) {
        int nl = ny + i * 16;
        size_t o = (size_t)(n0 + nl) * (Dx / 2) + (k0 / 2) + kp;
        T[o] = pack_h2(t[2 * kp][nl], t[2 * kp + 1][nl]);
    }
}

// ---------------------------------------------------------------------------
// FP16 single-term mma.sync GEMM with ldmatrix fragment loads.
// 512 thr, 128x256 tile, KT=128. A row-major [M,K]; B K-major [N,K].
// 16 warps (2m x 8n), 64x32 per warp. cp.async double buffering.
// Word-LD=68 -> LDSM phases hit all 32 banks (conflict-free).
// OUT_MODE 0: row-major [M,2048].  OUT_MODE 1: [B,H,S,HD] (BN=256 = 2 heads).
// ---------------------------------------------------------------------------
#define T_LDW 68
#define AT_W (128 * T_LDW)            // 8704 words
#define BT_W (256 * T_LDW)            // 17408 words
#define STG_W (AT_W + BT_W)           // 26112 words per stage
#define GEMM_DYN (2 * STG_W * 4)      // 208896 bytes

template <int OUT_MODE>
__global__ __launch_bounds__(512)
void hgemm256(const uint32_t* __restrict__ A, const uint32_t* __restrict__ W,
              float* __restrict__ C) {
    extern __shared__ uint32_t sm[];
    const int tid  = threadIdx.x;
    const int lane = tid & 31;
    const int warp = tid >> 5;
    const int wm   = warp & 1;
    const int wn   = warp >> 1;
    const int KW = Dx / 2;
    const size_t aoff = (size_t)blockIdx.y * 128 * KW;
    const size_t boff = (size_t)blockIdx.x * 256 * KW;

    const uint32_t smem_b = (uint32_t)__cvta_generic_to_shared(sm);

    // Per-thread ldmatrix base word offsets (within a stage):
    // A, frag mf: rows wm*64+mf*16+(lane&15); k-word +4 for lanes 16-31.
    const int a_ld = (wm * 64 + (lane & 15)) * T_LDW + ((lane >> 2) & 4);
    // B, frag pair p: cols wn*32+p*16+((lane&16)?8:0)+(lane&7); +4 words lanes 8-15/24-31.
    const int b_ld = (wn * 32 + ((lane >> 1) & 8) + (lane & 7)) * T_LDW
                   + ((lane >> 1) & 4);

    float acc[4][4][4];
#pragma unroll
    for (int i = 0; i < 4; ++i)
#pragma unroll
        for (int j = 0; j < 4; ++j)
#pragma unroll
            for (int t = 0; t < 4; ++t) acc[i][j][t] = 0.f;

    // Stage layout (words): A[AT_W] B[BT_W]. KT=128 -> 64 words per row.
    auto loadTiles = [&](int kt, int stg) {
        uint32_t* sb = sm + stg * STG_W;
        const int kw = kt / 2;
#pragma unroll
        for (int i = 0; i < 4; ++i) {
            int c = tid + 512 * i;
            int r = c >> 4, o = (c & 15) << 2;
            cpa16(sb + r * T_LDW + o, A + aoff + (size_t)r * KW + kw + o);
        }
#pragma unroll
        for (int i = 0; i < 8; ++i) {
            int c = tid + 512 * i;
            int r = c >> 4, o = (c & 15) << 2;
            cpa16(sb + AT_W + r * T_LDW + o, W + boff + (size_t)r * KW + kw + o);
        }
    };

    const int NT = Dx / 128;           // 16 chunks
    loadTiles(0, 0); cpa_commit();

    for (int it = 0; it < NT; ++it) {
        if (it + 1 < NT) {
            loadTiles((it + 1) * 128, (it + 1) & 1);
            cpa_commit();
            asm volatile("cp.async.wait_group 1;\n" ::: "memory");
        } else {
            asm volatile("cp.async.wait_group 0;\n" ::: "memory");
        }
        __syncthreads();

        const uint32_t abase = smem_b + ((it & 1) * STG_W) * 4;
        const uint32_t bbase = abase + AT_W * 4;

#pragma unroll
        for (int kk = 0; kk < 8; ++kk) {          // eight k16 slices
            const int kw0 = kk * 8;
            uint32_t af[4][4];
#pragma unroll
            for (int mf = 0; mf < 4; ++mf)
                ldsm4(af[mf], abase + (uint32_t)(a_ld + mf * 16 * T_LDW + kw0) * 4);
            uint32_t bf[4][2];
#pragma unroll
            for (int p = 0; p < 2; ++p) {
                uint32_t r[4];
                ldsm4(r, bbase + (uint32_t)(b_ld + p * 16 * T_LDW + kw0) * 4);
                bf[2 * p][0]     = r[0];
                bf[2 * p][1]     = r[1];
                bf[2 * p + 1][0] = r[2];
                bf[2 * p + 1][1] = r[3];
            }
#pragma unroll
            for (int mf = 0; mf < 4; ++mf)
#pragma unroll
                for (int nf = 0; nf < 4; ++nf)
                    mma_f16(acc[mf][nf], af[mf], bf[nf]);
        }
        __syncthreads();
    }

    // Epilogue
#pragma unroll
    for (int mf = 0; mf < 4; ++mf) {
#pragma unroll
        for (int nf = 0; nf < 4; ++nf) {
            int r0 = blockIdx.y * 128 + wm * 64 + mf * 16 + (lane >> 2);
            int r1 = r0 + 8;
            int cb = wn * 32 + nf * 8 + 2 * (lane & 3);
            float2 v0 = make_float2(acc[mf][nf][0], acc[mf][nf][1]);
            float2 v1 = make_float2(acc[mf][nf][2], acc[mf][nf][3]);
            if (OUT_MODE == 0) {
                *(float2*)(C + (size_t)r0 * Dx + blockIdx.x * 256 + cb) = v0;
                *(float2*)(C + (size_t)r1 * Dx + blockIdx.x * 256 + cb) = v1;
            } else {
                int h  = blockIdx.x * 2 + (cb >> 7);
                int hd = cb & 127;
                int b0 = r0 >> 11, s0 = r0 & 2047;
                int b1 = r1 >> 11, s1 = r1 & 2047;
                *(float2*)(C + (((size_t)b0 * Hx + h) * Sx + s0) * HDx + hd) = v0;
                *(float2*)(C + (((size_t)b1 * Hx + h) * Sx + s1) * HDx + hd) = v1;
            }
        }
    }
}

// ---------------------------------------------------------------------------
// RoPE + fp16 convert: reads fp32 q,k [bh][s][128], writes half2 pairs
// [bh*2048+s][64 words].
// ---------------------------------------------------------------------------
__global__ __launch_bounds__(128)
void rope_h_kernel(const float* __restrict__ q, const float* __restrict__ k,
                   uint32_t* __restrict__ qh, uint32_t* __restrict__ kh) {
    int row = blockIdx.x * 4 + (threadIdx.x >> 5);
    int j   = threadIdx.x & 31;
    int s   = row & (Sx - 1);
    float pos = (float)s;
    const float L = logf(10000.0f);
    float a0 = pos * expf(-L * (4.0f * j)        / 128.0f);
    float a1 = pos * expf(-L * (4.0f * j + 2.0f) / 128.0f);
    float c0, sn0, c1, sn1;
    sincosf(a0, &sn0, &c0);
    sincosf(a1, &sn1, &c1);

    const float* qr = q + (size_t)row * HDx;
    const float* kr = k + (size_t)row * HDx;
    size_t ob = (size_t)row * 64;

    {
        float x0 = qr[2*j], x1 = qr[2*j+1], y0 = qr[2*j+64], y1 = qr[2*j+65];
        qh[ob + j]      = pack_h2(x0 * c0 - y0 * sn0, x1 * c1 - y1 * sn1);
        qh[ob + 32 + j] = pack_h2(y0 * c0 + x0 * sn0, y1 * c1 + x1 * sn1);
    }
    {
        float x0 = kr[2*j], x1 = kr[2*j+1], y0 = kr[2*j+64], y1 = kr[2*j+65];
        kh[ob + j]      = pack_h2(x0 * c0 - y0 * sn0, x1 * c1 - y1 * sn1);
        kh[ob + 32 + j] = pack_h2(y0 * c0 + x0 * sn0, y1 * c1 + x1 * sn1);
    }
}

// ---------------------------------------------------------------------------
// V transpose + fp16: v fp32 [bh][s][128] -> vt [bh][d][1024 half2 words]
// ---------------------------------------------------------------------------
__global__ __launch_bounds__(256)
void vcvt_t_kernel(const float* __restrict__ v, uint32_t* __restrict__ T) {
    __shared__ float t[32][33];
    int s0 = blockIdx.x * 32, d0 = blockIdx.y * 32, bh = blockIdx.z;
    int tx = threadIdx.x & 31, ty = threadIdx.x >> 5;
#pragma unroll
    for (int i = 0; i < 4; ++i) {
        int sl = ty + i * 8;
        t[sl][tx] = v[((size_t)bh * Sx + s0 + sl) * HDx + d0 + tx];
    }
    __syncthreads();
    int r  = threadIdx.x >> 3;
    int wq = threadIdx.x & 7;
    size_t o = ((size_t)bh * HDx + d0 + r) * (Sx / 2) + (s0 >> 1) + 2 * wq;
    T[o]     = pack_h2(t[4*wq][r],   t[4*wq+1][r]);
    T[o + 1] = pack_h2(t[4*wq+2][r], t[4*wq+3][r]);
}

// ---------------------------------------------------------------------------
// Tensor-core flash attention (fp16 single-term, fp32 softmax, causal).
// Unchanged from R15 (risk control).
// ---------------------------------------------------------------------------
#define FQ_LD 68
#define FV_LD 36
#define FOQS (128 * FQ_LD)            // 8704
#define FK_W (64 * FQ_LD)             // 4352
#define FV_W (128 * FV_LD)            // 4608
#define FSTG_W (FK_W + FV_W)          // 8960
#define FLASH_DYN ((FOQS + 2 * FSTG_W) * 4)   // 106496 bytes

__global__ __launch_bounds__(256)
void flash_h(const uint32_t* __restrict__ Qh_, const uint32_t* __restrict__ Kh_,
             const uint32_t* __restrict__ Vh_, uint32_t* __restrict__ Oh_) {
    extern __shared__ uint32_t sw[];
    const int tid  = threadIdx.x;
    const int lane = tid & 31;
    const int warp = tid >> 5;
    const int qt   = 15 - blockIdx.x;     // heavy tiles first
    const int bh   = blockIdx.y;

    const size_t qbase = ((size_t)bh * Sx + qt * 128) * 64;
#pragma unroll
    for (int i = 0; i < 8; ++i) {
        int c = tid + 256 * i;
        int r = c >> 4, w4 = (c & 15) * 4;
        cpa16(sw + r * FQ_LD + w4, Qh_ + qbase + r * 64 + w4);
    }

    auto loadKV = [&](int kt, int stg) {
        uint32_t* sb = sw + FOQS + stg * FSTG_W;
        const size_t kbase = ((size_t)bh * Sx + kt * 64) * 64;
#pragma unroll
        for (int i = 0; i < 4; ++i) {
            int c = tid + 256 * i;
            int r = c >> 4, w4 = (c & 15) * 4;
            cpa16(sb + r * FQ_LD + w4, Kh_ + kbase + r * 64 + w4);
        }
        const size_t vbase = (size_t)bh * HDx * (Sx / 2) + kt * 32;
#pragma unroll
        for (int i = 0; i < 4; ++i) {
            int c = tid + 256 * i;
            int d = c >> 3, w4 = (c & 7) * 4;
            cpa16(sb + FK_W + d * FV_LD + w4, Vh_ + vbase + (size_t)d * (Sx / 2) + w4);
        }
    };

    float o[16][4];
#pragma unroll
    for (int i = 0; i < 16; ++i)
#pragma unroll
        for (int t = 0; t < 4; ++t) o[i][t] = 0.f;
    float m0 = -INFINITY, m1 = -INFINITY, l0 = 0.f, l1 = 0.f;

    const float scale = 0.08838834764831845f;
    const int ktmax = 2 * qt + 1;
    loadKV(0, 0); cpa_commit();

    for (int kt = 0; kt <= ktmax; ++kt) {
        const int stg = kt & 1;
        if (kt < ktmax) {
            loadKV(kt + 1, stg ^ 1);
            cpa_commit();
            asm volatile("cp.async.wait_group 1;\n" ::: "memory");
        } else {
            asm volatile("cp.async.wait_group 0;\n" ::: "memory");
        }
        __syncthreads();

        const uint32_t* Kb = sw + FOQS + stg * FSTG_W;
        const uint32_t* Vb = Kb + FK_W;
        const uint32_t* Qb = sw;

        float s[8][4];
#pragma unroll
        for (int nf = 0; nf < 8; ++nf)
#pragma unroll
            for (int t = 0; t < 4; ++t) s[nf][t] = 0.f;

#pragma unroll
        for (int ksl = 0; ksl < 8; ++ksl) {
            int ab = (warp * 16 + (lane >> 2)) * FQ_LD + ksl * 8 + (lane & 3);
            uint32_t qf[4] = {Qb[ab], Qb[ab + 8 * FQ_LD], Qb[ab + 4], Qb[ab + 8 * FQ_LD + 4]};
#pragma unroll
            for (int nf = 0; nf < 8; ++nf) {
                int bb = (nf * 8 + (lane >> 2)) * FQ_LD + ksl * 8 + (lane & 3);
                uint32_t kf[2] = {Kb[bb], Kb[bb + 4]};
                mma_f16(s[nf], qf, kf);
            }
        }

        const int rg0 = qt * 128 + warp * 16 + (lane >> 2);
        const int rg1 = rg0 + 8;
        const bool needmask = (kt >= 2 * qt);
#pragma unroll
        for (int nf = 0; nf < 8; ++nf) {
            int cb = kt * 64 + nf * 8 + 2 * (lane & 3);
#pragma unroll
            for (int t = 0; t < 4; ++t) {
                s[nf][t] *= scale;
                if (needmask) {
                    int col = cb + (t & 1);
                    int row = (t < 2) ? rg0 : rg1;
                    if (col > row) s[nf][t] = -1e30f;
                }
            }
        }

        float mx0 = -1e30f, mx1 = -1e30f;
#pragma unroll
        for (int nf = 0; nf < 8; ++nf) {
            mx0 = fmaxf(mx0, fmaxf(s[nf][0], s[nf][1]));
            mx1 = fmaxf(mx1, fmaxf(s[nf][2], s[nf][3]));
        }
        mx0 = fmaxf(mx0, __shfl_xor_sync(0xffffffffu, mx0, 1));
        mx0 = fmaxf(mx0, __shfl_xor_sync(0xffffffffu, mx0, 2));
        mx1 = fmaxf(mx1, __shfl_xor_sync(0xffffffffu, mx1, 1));
        mx1 = fmaxf(mx1, __shfl_xor_sync(0xffffffffu, mx1, 2));
        float mn0 = fmaxf(m0, mx0), mn1 = fmaxf(m1, mx1);
        float al0 = expf(m0 - mn0), al1 = expf(m1 - mn1);
        float ps0 = 0.f, ps1 = 0.f;
#pragma unroll
        for (int nf = 0; nf < 8; ++nf) {
            s[nf][0] = expf(s[nf][0] - mn0);
            s[nf][1] = expf(s[nf][1] - mn0);
            s[nf][2] = expf(s[nf][2] - mn1);
            s[nf][3] = expf(s[nf][3] - mn1);
            ps0 += s[nf][0] + s[nf][1];
            ps1 += s[nf][2] + s[nf][3];
        }
        ps0 += __shfl_xor_sync(0xffffffffu, ps0, 1);
        ps0 += __shfl_xor_sync(0xffffffffu, ps0, 2);
        ps1 += __shfl_xor_sync(0xffffffffu, ps1, 1);
        ps1 += __shfl_xor_sync(0xffffffffu, ps1, 2);
        l0 = l0 * al0 + ps0;
        l1 = l1 * al1 + ps1;
        m0 = mn0; m1 = mn1;
#pragma unroll
        for (int nf = 0; nf < 16; ++nf) {
            o[nf][0] *= al0; o[nf][1] *= al0;
            o[nf][2] *= al1; o[nf][3] *= al1;
        }

        uint32_t pf[4][4];
#pragma unroll
        for (int j = 0; j < 4; ++j) {
            pf[j][0] = pack_h2(s[2*j][0],   s[2*j][1]);
            pf[j][1] = pack_h2(s[2*j][2],   s[2*j][3]);
            pf[j][2] = pack_h2(s[2*j+1][0], s[2*j+1][1]);
            pf[j][3] = pack_h2(s[2*j+1][2], s[2*j+1][3]);
        }

#pragma unroll
        for (int j = 0; j < 4; ++j) {
#pragma unroll
            for (int nf = 0; nf < 16; ++nf) {
                int vb = (nf * 8 + (lane >> 2)) * FV_LD + j * 8 + (lane & 3);
                uint32_t vf[2] = {Vb[vb], Vb[vb + 4]};
                mma_f16(o[nf], pf[j], vf);
            }
        }
        __syncthreads();
    }

    const int b = bh >> 4;
    const int h = bh & 15;
    const float inv0 = 1.0f / l0;
    const float inv1 = 1.0f / l1;
    const int r0g = qt * 128 + warp * 16 + (lane >> 2);
    const int r1g = r0g + 8;
    const size_t row0 = ((size_t)b * Sx + r0g) * 1024 + h * 64;
    const size_t row1 = ((size_t)b * Sx + r1g) * 1024 + h * 64;
#pragma unroll
    for (int nf = 0; nf < 16; ++nf) {
        int dw = (nf * 8 + 2 * (lane & 3)) >> 1;
        Oh_[row0 + dw] = pack_h2(o[nf][0] * inv0, o[nf][1] * inv0);
        Oh_[row1 + dw] = pack_h2(o[nf][2] * inv1, o[nf][3] * inv1);
    }
}

// ---------------------------------------------------------------------------
// Launch
// ---------------------------------------------------------------------------
extern "C" void kernel_launch(void* const* d_in, const int* in_sizes, int n_in,
                              void* d_out, int out_size) {
    const float* hidden = (const float*)d_in[0];
    const float* Wq = (const float*)d_in[3];
    const float* Wk = (const float*)d_in[4];
    const float* Wv = (const float*)d_in[5];
    const float* Wo = (const float*)d_in[6];

    float *q, *k, *v;
    uint32_t *h16, *wq16, *wk16, *wv16, *wo16, *q16, *k16, *vt16;
    cudaGetSymbolAddress((void**)&q,    g_q);
    cudaGetSymbolAddress((void**)&k,    g_k);
    cudaGetSymbolAddress((void**)&v,    g_v);
    cudaGetSymbolAddress((void**)&h16,  g_h16);
    cudaGetSymbolAddress((void**)&wq16, g_wq16);
    cudaGetSymbolAddress((void**)&wk16, g_wk16);
    cudaGetSymbolAddress((void**)&wv16, g_wv16);
    cudaGetSymbolAddress((void**)&wo16, g_wo16);
    cudaGetSymbolAddress((void**)&q16,  g_q16);
    cudaGetSymbolAddress((void**)&k16,  g_k16);
    cudaGetSymbolAddress((void**)&vt16, g_vt16);

    cudaFuncSetAttribute(hgemm256<0>, cudaFuncAttributeMaxDynamicSharedMemorySize, GEMM_DYN);
    cudaFuncSetAttribute(hgemm256<1>, cudaFuncAttributeMaxDynamicSharedMemorySize, GEMM_DYN);
    cudaFuncSetAttribute(flash_h,     cudaFuncAttributeMaxDynamicSharedMemorySize, FLASH_DYN);

    dim3 gemm_grid(Dx / 256, Mx / 128);   // (8, 32)
    const int nH4 = (Mx * Dx) / 4;

    // Prep: fp16 convert hidden + all four weights (one fused launch)
    cvt_kernel<<<(nH4 + 255) / 256, 256>>>(hidden, h16, nH4);
    cvt_t4_kernel<<<dim3(Dx / 32, Dx / 32, 4), 256>>>(Wq, Wk, Wv, Wo,
                                                      wq16, wk16, wv16, wo16);

    // QKV projections -> [B,H,S,HD] fp32
    hgemm256<1><<<gemm_grid, 512, GEMM_DYN>>>(h16, wq16, q);
    hgemm256<1><<<gemm_grid, 512, GEMM_DYN>>>(h16, wk16, k);
    hgemm256<1><<<gemm_grid, 512, GEMM_DYN>>>(h16, wv16, v);

    // RoPE + fp16 convert q,k ; V transpose + fp16
    rope_h_kernel<<<(32 * Sx) / 4, 128>>>(q, k, q16, k16);
    vcvt_t_kernel<<<dim3(Sx / 32, HDx / 32, 32), 256>>>(v, vt16);

    // Flash attention (fp16 operands, fp32 softmax) -> ctx fp16 into h16
    flash_h<<<dim3(16, 32), 256, FLASH_DYN>>>(q16, k16, vt16, h16);

    // Output projection reads h16 directly.
    hgemm256<0><<<gemm_grid, 512, GEMM_DYN>>>(h16, wo16, (float*)d_out);
}